// round 2
// baseline (speedup 1.0000x reference)
#include <cuda_runtime.h>

// SpectralConv2d: B=16, C_IN=C_OUT=64, H=W=256, M=16
// Pipeline:
//  kA : X1[row,q] = sum_w x[row,w] * e^{-2pi i q w/256} / 256   (q=0..15, row=(b,c,h))
//  kB : X2[bc,m,q] = sum_h X1[h,q] * e^{-2pi i t(m) h/256}      (t: 0..15, 240..255)
//  kM : Y[b,d,m,q] = sum_c X2[b,c,m,q] * W[d,c,m,q]             (complex channel mix)
//  kCD: G[h,q] = sum_m Y[m,q] e^{+2pi i t(m) h/256};
//       out[h,w] = (1/256)[Re G[h,0] + 2 sum_{q=1..15}(Gre cos - Gim sin)]

#define NROWS (16*64*256)   // 262144
#define NBC   (16*64)       // 1024

__device__ float  g_X1[NROWS * 32];        // [row][2q interleaved re/im]
__device__ float2 g_X2[NBC * 32 * 16];     // [bc][m][q]
__device__ float2 g_Y [NBC * 32 * 16];     // [bd][m][q]

// ---------------- Stage A: w-DFT (GEMM [rows x 256] * E[256 x 32]) ----------------
// CTA: 64 rows, 256 threads. thread = (row r=tid>>2, comp-group g=tid&3 -> comps 8g..8g+7)
__global__ __launch_bounds__(256) void kA(const float* __restrict__ x) {
    extern __shared__ float smem[];
    float* xs = smem;              // 64 rows, pitch 260 floats
    float* Es = smem + 64 * 260;   // [w][32]
    const int tid = threadIdx.x;
    const size_t rowBase = (size_t)blockIdx.x * 64;

    // load x tile (64x256 contiguous) as float4, store with pitch 260 (bank-safe, 16B aligned)
    const float4* xg = (const float4*)(x + rowBase * 256);
    #pragma unroll
    for (int i = tid; i < 64 * 64; i += 256) {
        float4 v = xg[i];
        int r = i >> 6;
        int wq = (i & 63) << 2;
        float* dst = &xs[r * 260 + wq];
        dst[0] = v.x; dst[1] = v.y; dst[2] = v.z; dst[3] = v.w;
    }
    // build E: E[w][2q] = cos(2pi q w/256)/256, E[w][2q+1] = -sin(...)/256
    for (int i = tid; i < 256 * 32; i += 256) {
        int w = i >> 5, c = i & 31, q = c >> 1;
        float s, co;
        sincospif((float)(q * w) * (1.0f / 128.0f), &s, &co);
        Es[i] = (c & 1) ? (-s * (1.0f / 256.0f)) : (co * (1.0f / 256.0f));
    }
    __syncthreads();

    const int g = tid & 3, r = tid >> 2;
    float acc[8];
    #pragma unroll
    for (int c = 0; c < 8; c++) acc[c] = 0.0f;
    const float* xr = &xs[r * 260];

    #pragma unroll 4
    for (int wb = 0; wb < 64; wb++) {
        float4 xv = *(const float4*)(xr + wb * 4);
        #pragma unroll
        for (int i = 0; i < 4; i++) {
            float xvv = (&xv.x)[i];
            const float4* ep = (const float4*)&Es[(wb * 4 + i) * 32 + g * 8];
            float4 e0 = ep[0], e1 = ep[1];
            acc[0] += xvv * e0.x; acc[1] += xvv * e0.y;
            acc[2] += xvv * e0.z; acc[3] += xvv * e0.w;
            acc[4] += xvv * e1.x; acc[5] += xvv * e1.y;
            acc[6] += xvv * e1.z; acc[7] += xvv * e1.w;
        }
    }
    float* out = &g_X1[(rowBase + r) * 32 + g * 8];
    *(float4*)out       = make_float4(acc[0], acc[1], acc[2], acc[3]);
    *(float4*)(out + 4) = make_float4(acc[4], acc[5], acc[6], acc[7]);
}

// ---------------- Stage B: h-DFT at 32 kept t's ----------------
__global__ __launch_bounds__(256) void kB() {
    __shared__ float  X1s[256 * 32];
    __shared__ float2 tw[256];
    const int tid = threadIdx.x;
    const size_t bc = blockIdx.x;

    const float4* src = (const float4*)&g_X1[bc * 8192];
    #pragma unroll
    for (int i = 0; i < 8; i++) ((float4*)X1s)[tid + i * 256] = src[tid + i * 256];
    {
        float s, c;
        sincospif((float)tid * (1.0f / 128.0f), &s, &c);
        tw[tid] = make_float2(c, s);   // e^{+2pi i tid/256}
    }
    __syncthreads();

    #pragma unroll
    for (int k = 0; k < 2; k++) {
        int task = tid + k * 256;            // 512 tasks = 32 m x 16 q
        int q = task & 15;
        int m = task >> 4;
        int t = (m < 16) ? m : (224 + m);    // 240..255 for m=16..31
        float ar = 0.0f, ai = 0.0f;
        #pragma unroll 4
        for (int h = 0; h < 256; h++) {
            float2 e = tw[(t * h) & 255];
            float2 v = *(const float2*)&X1s[h * 32 + 2 * q];
            // multiply by e^{-i theta}: (vr + i vi)(c - i s)
            ar += v.x * e.x + v.y * e.y;
            ai += v.y * e.x - v.x * e.y;
        }
        g_X2[(bc * 32 + m) * 16 + q] = make_float2(ar, ai);
    }
}

// ---------------- Channel mixing: per-mode complex [16x64]*[64x64] ----------------
__global__ __launch_bounds__(256) void kM(const float* __restrict__ w1,
                                          const float* __restrict__ w2) {
    __shared__ float2 Xs[16 * 64];
    __shared__ float2 Ws[64 * 65];           // pitch 65 to dodge bank conflicts
    const int tid = threadIdx.x;
    const int m = blockIdx.x >> 4;
    const int q = blockIdx.x & 15;
    const float* wsrc = (m < 16) ? w1 : w2;
    const int t_w = (m < 16) ? m : (m - 16);

    for (int i = tid; i < 1024; i += 256) {
        int b = i >> 6, c = i & 63;
        Xs[i] = g_X2[((size_t)(b * 64 + c) * 32 + m) * 16 + q];
    }
    for (int i = tid; i < 4096; i += 256) {
        int d = i >> 6, c = i & 63;
        const float* p = wsrc + ((size_t)(d * 64 + c) * 256 + t_w * 16 + q) * 2;
        Ws[d * 65 + c] = make_float2(p[0], p[1]);
    }
    __syncthreads();

    const int b = tid >> 4;
    const int dl = tid & 15;
    float2 acc[4];
    #pragma unroll
    for (int j = 0; j < 4; j++) acc[j] = make_float2(0.0f, 0.0f);
    #pragma unroll 4
    for (int c = 0; c < 64; c++) {
        float2 xv = Xs[b * 64 + c];
        #pragma unroll
        for (int j = 0; j < 4; j++) {
            float2 wv = Ws[(dl + 16 * j) * 65 + c];
            acc[j].x += xv.x * wv.x - xv.y * wv.y;
            acc[j].y += xv.x * wv.y + xv.y * wv.x;
        }
    }
    #pragma unroll
    for (int j = 0; j < 4; j++) {
        int d = dl + 16 * j;
        g_Y[((size_t)(b * 64 + d) * 32 + m) * 16 + q] = acc[j];
    }
}

// ---------------- Inverse: G build + output GEMM [256h x 32] * [32 x 256w] ----------------
__global__ __launch_bounds__(256) void kCD(float* __restrict__ out) {
    extern __shared__ float smem[];
    float2* tw  = (float2*)smem;            // 256
    float2* Ys  = (float2*)(smem + 512);    // 512 [m][q]
    float*  Gs  = smem + 1536;              // [h][32]
    float*  Dts = smem + 1536 + 8192;       // [c][w]
    const int tid = threadIdx.x;
    const size_t bd = blockIdx.x;

    {
        float s, c;
        sincospif((float)tid * (1.0f / 128.0f), &s, &c);
        tw[tid] = make_float2(c, s);
    }
    const float4* ysrc = (const float4*)&g_Y[bd * 512];
    ((float4*)Ys)[tid] = ysrc[tid];          // 512 float2 = 256 float4
    __syncthreads();

    // Dts[c][w]: c=2q -> a_q cos(2pi q w/256)/256 ; c=2q+1 -> -a_q sin(...)/256 (q=0 im -> 0)
    for (int i = tid; i < 8192; i += 256) {
        int w = i & 255, c = i >> 8, q = c >> 1;
        float2 e = tw[(q * w) & 255];
        float a = (q == 0) ? (1.0f / 256.0f) : (2.0f / 256.0f);
        float v;
        if (c & 1) v = (q == 0) ? 0.0f : (-a * e.y);
        else       v = a * e.x;
        Dts[c * 256 + w] = v;
    }
    // Gs[h][2q(+1)] = sum_m Y[m,q] * e^{+2pi i t(m) h/256}
    #pragma unroll
    for (int k = 0; k < 16; k++) {
        int task = tid + k * 256;            // 4096 = 256h x 16q
        int q = task & 15;
        int h = task >> 4;
        float gr = 0.0f, gi = 0.0f;
        #pragma unroll 8
        for (int mm = 0; mm < 32; mm++) {
            int t = (mm < 16) ? mm : (224 + mm);
            float2 e = tw[(t * h) & 255];
            float2 y = Ys[mm * 16 + q];
            gr += y.x * e.x - y.y * e.y;
            gi += y.x * e.y + y.y * e.x;
        }
        *(float2*)&Gs[h * 32 + 2 * q] = make_float2(gr, gi);
    }
    __syncthreads();

    // thread per w: Dt column in registers, G rows broadcast from smem, coalesced stores
    const int w = tid;
    float dt[32];
    #pragma unroll
    for (int c = 0; c < 32; c++) dt[c] = Dts[c * 256 + w];
    float* orow = out + bd * 65536 + w;
    #pragma unroll 2
    for (int h = 0; h < 256; h++) {
        const float* gp = &Gs[h * 32];
        float acc = 0.0f;
        #pragma unroll
        for (int c = 0; c < 32; c++) acc += gp[c] * dt[c];
        orow[h * 256] = acc;
    }
}

extern "C" void kernel_launch(void* const* d_in, const int* in_sizes, int n_in,
                              void* d_out, int out_size) {
    const float* x  = (const float*)d_in[0];
    const float* w1 = (const float*)d_in[1];
    const float* w2 = (const float*)d_in[2];
    float* out = (float*)d_out;

    const int SMEM_A  = (64 * 260 + 256 * 32) * 4;              // 99328 B
    const int SMEM_CD = (512 + 1024 + 8192 + 8192) * 4;         // 71680 B
    cudaFuncSetAttribute(kA,  cudaFuncAttributeMaxDynamicSharedMemorySize, SMEM_A);
    cudaFuncSetAttribute(kCD, cudaFuncAttributeMaxDynamicSharedMemorySize, SMEM_CD);

    kA<<<NROWS / 64, 256, SMEM_A>>>(x);
    kB<<<NBC, 256>>>();
    kM<<<512, 256>>>(w1, w2);
    kCD<<<NBC, 256, SMEM_CD>>>(out);
}

// round 3
// speedup vs baseline: 1.1264x; 1.1264x over previous
#include <cuda_runtime.h>

// SpectralConv2d: B=16, C_IN=C_OUT=64, H=W=256, M=16
// f32x2-packed pruned-DFT pipeline:
//  kA : X1[row,q] = (1/256) sum_w x[row,w] e^{-2pi i q w/256}, q<16    (packed re/im)
//  kB : X2[bc,m,q] = sum_h X1[h,q] e^{-2pi i t(m) h/256}
//  kM : Y[b,d,m,q] = sum_c X2[b,c,m,q] * W[d,c,m,q]
//  kCD: G[h,q] = sum_m Y[m,q] e^{+2pi i t(m) h/256};  Gp = (a*Gre, -a*Gim)
//       out[h,w'] = C+S, out[h,256-w'] = C-S  with (C,S) += Gp * (cos,sin)  (w-symmetry)

#define NROWS (16*64*256)   // 262144
#define NBC   (16*64)       // 1024

typedef unsigned long long u64;

__device__ float  g_X1[NROWS * 32];        // [row][2q interleaved re/im]
__device__ float2 g_X2[NBC * 32 * 16];     // [bc][m][q]
__device__ float2 g_Y [NBC * 32 * 16];     // [bd][m][q]

__device__ __forceinline__ u64 pack2(float lo, float hi) {
    u64 r; asm("mov.b64 %0, {%1,%2};" : "=l"(r) : "f"(lo), "f"(hi)); return r;
}
__device__ __forceinline__ float2 unpack2(u64 v) {
    float lo, hi; asm("mov.b64 {%0,%1}, %2;" : "=f"(lo), "=f"(hi) : "l"(v));
    return make_float2(lo, hi);
}
__device__ __forceinline__ u64 fma2(u64 a, u64 b, u64 c) {
    u64 d; asm("fma.rn.f32x2 %0, %1, %2, %3;" : "=l"(d) : "l"(a), "l"(b), "l"(c)); return d;
}
__device__ __forceinline__ u64 add2(u64 a, u64 b) {
    u64 d; asm("add.rn.f32x2 %0, %1, %2;" : "=l"(d) : "l"(a), "l"(b)); return d;
}

// ---------------- Stage A: w-DFT, thread tile = 2 rows x 8 q, f32x2 (re,im) accs ----
// CTA: 64 rows, 64 threads. smem: x tile pitch 257 (odd -> <=2-way on stride-2 row reads)
__global__ __launch_bounds__(64) void kA(const float* __restrict__ x) {
    extern __shared__ float sm[];
    float* xs = sm;                          // 64 x 257
    u64*   E2 = (u64*)(sm + 64 * 257);       // [w][16] packed (cos/256, -sin/256)
    const int tid = threadIdx.x;
    const size_t rowBase = (size_t)blockIdx.x * 64;

    // each thread loads one full row; scalar STS at odd pitch => conflict-free banks
    {
        const float4* src = (const float4*)(x + (rowBase + tid) * 256);
        float* dst = xs + tid * 257;
        #pragma unroll 8
        for (int k = 0; k < 64; k++) {
            float4 v = src[k];
            dst[4*k] = v.x; dst[4*k+1] = v.y; dst[4*k+2] = v.z; dst[4*k+3] = v.w;
        }
    }
    for (int i = tid; i < 256 * 16; i += 64) {
        int w = i >> 4, q = i & 15;
        float s, c;
        sincospif((float)(q * w) * (1.0f / 128.0f), &s, &c);
        E2[i] = pack2(c * (1.0f / 256.0f), -s * (1.0f / 256.0f));
    }
    __syncthreads();

    const int rt = tid & 31;      // 32 row-pairs
    const int qg = tid >> 5;      // 2 q-groups of 8  (uniform per warp)
    const float* x0 = xs + (2 * rt) * 257;
    const float* x1 = xs + (2 * rt + 1) * 257;

    u64 acc[16];
    #pragma unroll
    for (int j = 0; j < 16; j++) acc[j] = 0ull;

    const ulonglong2* Eg = (const ulonglong2*)(E2 + qg * 8);
    #pragma unroll 4
    for (int w = 0; w < 256; w++) {
        u64 xa = pack2(x0[w], x0[w]);
        u64 xb = pack2(x1[w], x1[w]);
        ulonglong2 e01 = Eg[w * 8 + 0];
        ulonglong2 e23 = Eg[w * 8 + 1];
        ulonglong2 e45 = Eg[w * 8 + 2];
        ulonglong2 e67 = Eg[w * 8 + 3];
        acc[0]  = fma2(xa, e01.x, acc[0]);  acc[8]  = fma2(xb, e01.x, acc[8]);
        acc[1]  = fma2(xa, e01.y, acc[1]);  acc[9]  = fma2(xb, e01.y, acc[9]);
        acc[2]  = fma2(xa, e23.x, acc[2]);  acc[10] = fma2(xb, e23.x, acc[10]);
        acc[3]  = fma2(xa, e23.y, acc[3]);  acc[11] = fma2(xb, e23.y, acc[11]);
        acc[4]  = fma2(xa, e45.x, acc[4]);  acc[12] = fma2(xb, e45.x, acc[12]);
        acc[5]  = fma2(xa, e45.y, acc[5]);  acc[13] = fma2(xb, e45.y, acc[13]);
        acc[6]  = fma2(xa, e67.x, acc[6]);  acc[14] = fma2(xb, e67.x, acc[14]);
        acc[7]  = fma2(xa, e67.y, acc[7]);  acc[15] = fma2(xb, e67.y, acc[15]);
    }

    float* o0 = &g_X1[(rowBase + 2 * rt) * 32 + qg * 16];
    float* o1 = o0 + 32;
    #pragma unroll
    for (int j = 0; j < 8; j++) {
        *(float2*)(o0 + 2 * j) = unpack2(acc[j]);
        *(float2*)(o1 + 2 * j) = unpack2(acc[8 + j]);
    }
}

// ---------------- Stage B: h-DFT at 32 kept t's, thread = (m, q-pair) ----------------
__global__ __launch_bounds__(256) void kB() {
    __shared__ float X1s[256 * 32];
    __shared__ ulonglong2 tw4[256];       // ((c,-s),(s,c)) of +2pi a/256
    const int tid = threadIdx.x;
    const size_t bc = blockIdx.x;

    const float4* src = (const float4*)&g_X1[bc * 8192];
    float4* dst = (float4*)X1s;
    #pragma unroll
    for (int i = 0; i < 8; i++) dst[tid + i * 256] = src[tid + i * 256];
    {
        float s, c;
        sincospif((float)tid * (1.0f / 128.0f), &s, &c);
        ulonglong2 t; t.x = pack2(c, -s); t.y = pack2(s, c);
        tw4[tid] = t;
    }
    __syncthreads();

    const int m = tid >> 3, qp = tid & 7;
    const int t = (m < 16) ? m : (224 + m);
    u64 a0 = 0, a1 = 0, a2 = 0, a3 = 0;

    #pragma unroll 4
    for (int h = 0; h < 256; h++) {
        ulonglong2 tw = tw4[(t * h) & 255];
        float4 v = *(const float4*)&X1s[h * 32 + 4 * qp];
        a0 = fma2(pack2(v.x, v.x), tw.x, a0);
        a1 = fma2(pack2(v.y, v.y), tw.y, a1);
        a2 = fma2(pack2(v.z, v.z), tw.x, a2);
        a3 = fma2(pack2(v.w, v.w), tw.y, a3);
    }
    float2 r0 = unpack2(add2(a0, a1));
    float2 r1 = unpack2(add2(a2, a3));
    *(float4*)&g_X2[((size_t)(bc * 32 + m)) * 16 + 2 * qp] =
        make_float4(r0.x, r0.y, r1.x, r1.y);
}

// ---------------- Channel mixing: per-(m,q) complex [16x64]*[64x64], packed weights ---
__global__ __launch_bounds__(256) void kM(const float* __restrict__ w1,
                                          const float* __restrict__ w2) {
    extern __shared__ char smM[];
    float2* Xs = (float2*)smM;                       // [b*64+c]
    ulonglong2* Wpk = (ulonglong2*)(smM + 1024 * 8); // [c*64+d] = ((wr,wi),(-wi,wr))
    const int tid = threadIdx.x;
    const int m = blockIdx.x >> 4;
    const int q = blockIdx.x & 15;
    const float* wsrc = (m < 16) ? w1 : w2;
    const int t_w = (m < 16) ? m : (m - 16);

    for (int i = tid; i < 1024; i += 256) {
        int b = i >> 6, c = i & 63;
        Xs[i] = g_X2[((size_t)(b * 64 + c) * 32 + m) * 16 + q];
    }
    for (int i = tid; i < 4096; i += 256) {
        int c = i >> 6, d = i & 63;
        const float* p = wsrc + ((size_t)(d * 64 + c) * 256 + t_w * 16 + q) * 2;
        float wr = p[0], wi = p[1];
        ulonglong2 v; v.x = pack2(wr, wi); v.y = pack2(-wi, wr);
        Wpk[c * 64 + d] = v;
    }
    __syncthreads();

    const int b = tid >> 4;
    const int dl = tid & 15;
    u64 accA[4], accB[4];
    #pragma unroll
    for (int j = 0; j < 4; j++) { accA[j] = 0ull; accB[j] = 0ull; }

    #pragma unroll 4
    for (int c = 0; c < 64; c++) {
        float2 xv = Xs[b * 64 + c];
        u64 xr = pack2(xv.x, xv.x), xi = pack2(xv.y, xv.y);
        #pragma unroll
        for (int j = 0; j < 4; j++) {
            ulonglong2 wv = Wpk[c * 64 + dl + 16 * j];
            accA[j] = fma2(xr, wv.x, accA[j]);
            accB[j] = fma2(xi, wv.y, accB[j]);
        }
    }
    #pragma unroll
    for (int j = 0; j < 4; j++) {
        int d = dl + 16 * j;
        g_Y[((size_t)(b * 64 + d) * 32 + m) * 16 + q] = unpack2(add2(accA[j], accB[j]));
    }
}

// ---------------- Inverse: G build + symmetric output GEMM ----------------
__global__ __launch_bounds__(256) void kCD(float* __restrict__ out) {
    __shared__ ulonglong2 tw4[256];      // ((c,s),(-s,c)) of +2pi a/256
    __shared__ float2 Ys[512];           // [m][q]
    __shared__ float2 Gp[16 * 258];      // [q][h] = (a*Gre, -a*Gim), pitch 258
    const int tid = threadIdx.x;
    const size_t bd = blockIdx.x;

    {
        float s, c;
        sincospif((float)tid * (1.0f / 128.0f), &s, &c);
        ulonglong2 t; t.x = pack2(c, s); t.y = pack2(-s, c);
        tw4[tid] = t;
    }
    ((float4*)Ys)[tid] = ((const float4*)&g_Y[bd * 512])[tid];
    __syncthreads();

    // G build: task = (h, q-group of 4), 4 iters
    #pragma unroll
    for (int it = 0; it < 4; it++) {
        int task = tid + it * 256;
        int h = task >> 2, qg = task & 3;
        u64 ga[4] = {0, 0, 0, 0}, gb[4] = {0, 0, 0, 0};
        #pragma unroll 4
        for (int mm = 0; mm < 32; mm++) {
            int t = (mm < 16) ? mm : (224 + mm);
            ulonglong2 tw = tw4[(t * h) & 255];
            #pragma unroll
            for (int j = 0; j < 4; j++) {
                float2 y = Ys[mm * 16 + qg * 4 + j];
                ga[j] = fma2(pack2(y.x, y.x), tw.x, ga[j]);
                gb[j] = fma2(pack2(y.y, y.y), tw.y, gb[j]);
            }
        }
        #pragma unroll
        for (int j = 0; j < 4; j++) {
            int q = qg * 4 + j;
            float a = (q == 0) ? (1.0f / 256.0f) : (2.0f / 256.0f);
            float2 g = unpack2(add2(ga[j], gb[j]));
            Gp[q * 258 + h] = make_float2(a * g.x, -a * g.y);
        }
    }
    __syncthreads();

    // out GEMM with w-symmetry: thread = (w'=tid&127, h-half), twiddles in registers
    const int w2 = tid & 127;
    const int hg = tid >> 7;
    u64 twc[16];
    #pragma unroll
    for (int q = 0; q < 16; q++) twc[q] = tw4[(q * w2) & 255].x;   // (cos, sin)

    float* ob = out + bd * 65536;
    const int h0 = hg * 128;
    #pragma unroll 2
    for (int hh = h0; hh < h0 + 128; hh += 2) {
        u64 c0 = 0, c1 = 0;
        #pragma unroll
        for (int q = 0; q < 16; q++) {
            ulonglong2 g = *(const ulonglong2*)&Gp[q * 258 + hh];  // broadcast
            c0 = fma2(g.x, twc[q], c0);
            c1 = fma2(g.y, twc[q], c1);
        }
        float2 r0 = unpack2(c0), r1 = unpack2(c1);
        ob[hh * 256 + w2]       = r0.x + r0.y;
        ob[(hh + 1) * 256 + w2] = r1.x + r1.y;
        if (w2) {
            ob[hh * 256 + 256 - w2]       = r0.x - r0.y;
            ob[(hh + 1) * 256 + 256 - w2] = r1.x - r1.y;
        }
    }
    // w = 128 column: cos(pi q) = (-1)^q, sin = 0
    {
        int h = tid;
        float acc = 0.0f;
        #pragma unroll
        for (int q = 0; q < 16; q++) {
            float v = Gp[q * 258 + h].x;
            acc += (q & 1) ? -v : v;
        }
        ob[h * 256 + 128] = acc;
    }
}

extern "C" void kernel_launch(void* const* d_in, const int* in_sizes, int n_in,
                              void* d_out, int out_size) {
    const float* x  = (const float*)d_in[0];
    const float* w1 = (const float*)d_in[1];
    const float* w2 = (const float*)d_in[2];
    float* out = (float*)d_out;

    const int SMEM_A = 64 * 257 * 4 + 256 * 16 * 8;   // 98560
    const int SMEM_M = 1024 * 8 + 4096 * 16;          // 73728
    cudaFuncSetAttribute(kA, cudaFuncAttributeMaxDynamicSharedMemorySize, SMEM_A);
    cudaFuncSetAttribute(kM, cudaFuncAttributeMaxDynamicSharedMemorySize, SMEM_M);

    kA<<<NROWS / 64, 64, SMEM_A>>>(x);
    kB<<<NBC, 256>>>();
    kM<<<512, 256, SMEM_M>>>(w1, w2);
    kCD<<<NBC, 256>>>(out);
}

// round 6
// speedup vs baseline: 1.2623x; 1.1206x over previous
#include <cuda_runtime.h>

// SpectralConv2d: B=16, C_IN=C_OUT=64, H=W=256, M=16
// Fused pruned-DFT pipeline with mirror symmetry, f32x2 packed math:
//  kAB: per (b,c): X1[h,q] in smem (w-symmetry, 129 iters), then h-DFT at
//       m'=0..16 producing X2[+m'] and X2[-m'] from shared cos/sin sums.
//  kM : per-(m,q) complex channel mix [16x64]*[64x64].
//  kCD: G[h,q] = sum over 17 m'-pairs (P cos + Qv sin); inverse w with symmetry.

#define NBC   (16*64)       // 1024

typedef unsigned long long u64;

__device__ float2 g_X2[NBC * 32 * 16];     // [bc][m][q]
__device__ float2 g_Y [NBC * 32 * 16];     // [bd][m][q]

__device__ __forceinline__ u64 pack2(float lo, float hi) {
    u64 r; asm("mov.b64 %0, {%1,%2};" : "=l"(r) : "f"(lo), "f"(hi)); return r;
}
__device__ __forceinline__ float2 unpack2(u64 v) {
    float lo, hi; asm("mov.b64 {%0,%1}, %2;" : "=f"(lo), "=f"(hi) : "l"(v));
    return make_float2(lo, hi);
}
__device__ __forceinline__ u64 fma2(u64 a, u64 b, u64 c) {
    u64 d; asm("fma.rn.f32x2 %0, %1, %2, %3;" : "=l"(d) : "l"(a), "l"(b), "l"(c)); return d;
}

// ================= Fused stage A+B: CTA per (b,c) =================
// smem layout (bytes):
//   twcs2 : ulonglong2[256] @0       ((c,c),(s,s))            4096
//   E     : u64[129*16]     @4096    (cos*k, -sin*k)          16512
//   X1s   : u64[256*18]     @20608   [h][q] packed (re,im)    36864
//   twb   : float2[256]     @57472   (c,s) base               2048
//   xs    : float[128*260]  @59520   swizzled x tile          133120  -> 192640
__global__ __launch_bounds__(256) void kAB(const float* __restrict__ x) {
    extern __shared__ char sm[];
    ulonglong2* twcs2 = (ulonglong2*)sm;
    u64*        E     = (u64*)(sm + 4096);
    u64*        X1s   = (u64*)(sm + 20608);
    float2*     twb   = (float2*)(sm + 57472);
    float*      xs    = (float*)(sm + 59520);

    const int tid = threadIdx.x;
    const size_t bc = blockIdx.x;

    {
        float s, c;
        sincospif((float)tid * (1.0f / 128.0f), &s, &c);
        twb[tid] = make_float2(c, s);
        ulonglong2 t; t.x = pack2(c, c); t.y = pack2(s, s);
        twcs2[tid] = t;
    }
    __syncthreads();
    for (int i = tid; i < 129 * 16; i += 256) {
        int wp = i >> 4, q = i & 15;
        float2 b = twb[(q * wp) & 255];
        float sc = (wp == 0 || wp == 128) ? (0.5f / 256.0f) : (1.0f / 256.0f);
        E[i] = pack2(b.x * sc, -b.y * sc);
    }

    const int row  = tid & 127;
    const int qg   = tid >> 7;               // warp-uniform (2 groups of 8 q)
    const int pxor = (row >> 3) & 3;
    const int rowbase = row * 260;

    for (int pass = 0; pass < 2; pass++) {
        __syncthreads();   // xs free (prev pass readers done) / E visible (pass 0)
        // load 128 rows of x, float4, swizzled: c4 -> c4 ^ ((r>>3)&3)
        const float4* src = (const float4*)(x + bc * 65536 + pass * 32768);
        #pragma unroll 8
        for (int k = 0; k < 32; k++) {
            int idx = tid + k * 256;
            float4 v = src[idx];
            int r = idx >> 6;
            int c4 = idx & 63;
            *(float4*)(xs + r * 260 + ((c4 ^ ((r >> 3) & 3)) << 2)) = v;
        }
        __syncthreads();

        u64 acc[8];
        #pragma unroll
        for (int j = 0; j < 8; j++) acc[j] = 0ull;

        #pragma unroll 1
        for (int wp = 0; wp <= 128; wp++) {
            int wm  = (256 - wp) & 255;
            int c4a = wp >> 2,  ja = wp & 3;
            int c4b = wm >> 2,  jb = wm & 3;
            float xa = xs[rowbase + ((c4a ^ pxor) << 2) + ja];
            float xb = xs[rowbase + ((c4b ^ pxor) << 2) + jb];
            u64 sd = pack2(xa + xb, xa - xb);
            const ulonglong2* ep = (const ulonglong2*)(E + wp * 16 + qg * 8);
            ulonglong2 e0 = ep[0], e1 = ep[1], e2 = ep[2], e3 = ep[3];
            acc[0] = fma2(sd, e0.x, acc[0]);
            acc[1] = fma2(sd, e0.y, acc[1]);
            acc[2] = fma2(sd, e1.x, acc[2]);
            acc[3] = fma2(sd, e1.y, acc[3]);
            acc[4] = fma2(sd, e2.x, acc[4]);
            acc[5] = fma2(sd, e2.y, acc[5]);
            acc[6] = fma2(sd, e3.x, acc[6]);
            acc[7] = fma2(sd, e3.y, acc[7]);
        }

        u64* xo = X1s + (size_t)(pass * 128 + row) * 18 + qg * 8;
        #pragma unroll
        for (int j = 0; j < 4; j++) {
            ulonglong2 v; v.x = acc[2 * j]; v.y = acc[2 * j + 1];
            ((ulonglong2*)xo)[j] = v;
        }
    }
    __syncthreads();

    // Stage B: X2[t] for t = +m', -m' from A=sum X1 cos, B=sum X1 sin
    for (int task = tid; task < 272; task += 256) {
        int q = task & 15, mp = task >> 4;   // mp = 0..16
        u64 A = 0ull, Bm = 0ull;
        #pragma unroll 4
        for (int h = 0; h < 256; h++) {
            u64 v = X1s[h * 18 + q];
            ulonglong2 t = twcs2[(mp * h) & 255];
            A  = fma2(v, t.x, A);
            Bm = fma2(v, t.y, Bm);
        }
        float2 a = unpack2(A), b = unpack2(Bm);
        float2* dst = g_X2 + bc * 512;
        if (mp <= 15) dst[mp * 16 + q]        = make_float2(a.x + b.y, a.y - b.x);
        if (mp >= 1)  dst[(32 - mp) * 16 + q] = make_float2(a.x - b.y, a.y + b.x);
    }
}

// ================= Channel mixing (unchanged from R2) =================
__global__ __launch_bounds__(256) void kM(const float* __restrict__ w1,
                                          const float* __restrict__ w2) {
    extern __shared__ char smM[];
    float2* Xs = (float2*)smM;                       // [b*64+c]
    ulonglong2* Wpk = (ulonglong2*)(smM + 1024 * 8); // [c*64+d] = ((wr,wi),(-wi,wr))
    const int tid = threadIdx.x;
    const int m = blockIdx.x >> 4;
    const int q = blockIdx.x & 15;
    const float* wsrc = (m < 16) ? w1 : w2;
    const int t_w = (m < 16) ? m : (m - 16);

    for (int i = tid; i < 1024; i += 256) {
        int b = i >> 6, c = i & 63;
        Xs[i] = g_X2[((size_t)(b * 64 + c) * 32 + m) * 16 + q];
    }
    for (int i = tid; i < 4096; i += 256) {
        int c = i >> 6, d = i & 63;
        const float* p = wsrc + ((size_t)(d * 64 + c) * 256 + t_w * 16 + q) * 2;
        float wr = p[0], wi = p[1];
        ulonglong2 v; v.x = pack2(wr, wi); v.y = pack2(-wi, wr);
        Wpk[c * 64 + d] = v;
    }
    __syncthreads();

    const int b = tid >> 4;
    const int dl = tid & 15;
    u64 accA[4], accB[4];
    #pragma unroll
    for (int j = 0; j < 4; j++) { accA[j] = 0ull; accB[j] = 0ull; }

    #pragma unroll 4
    for (int c = 0; c < 64; c++) {
        float2 xv = Xs[b * 64 + c];
        u64 xr = pack2(xv.x, xv.x), xi = pack2(xv.y, xv.y);
        #pragma unroll
        for (int j = 0; j < 4; j++) {
            ulonglong2 wv = Wpk[c * 64 + dl + 16 * j];
            accA[j] = fma2(xr, wv.x, accA[j]);
            accB[j] = fma2(xi, wv.y, accB[j]);
        }
    }
    #pragma unroll
    for (int j = 0; j < 4; j++) {
        int d = dl + 16 * j;
        float2 ra = unpack2(accA[j]), rb = unpack2(accB[j]);
        g_Y[((size_t)(b * 64 + d) * 32 + m) * 16 + q] =
            make_float2(ra.x + rb.x, ra.y + rb.y);
    }
}

// ================= Inverse: symmetric G build + symmetric w-GEMM =================
__global__ __launch_bounds__(256) void kCD(float* __restrict__ out) {
    __shared__ u64        twcs[256];     // (c, s)
    __shared__ ulonglong2 tw2[256];      // ((c,c),(s,s))
    __shared__ float2     Ys[512];       // [m][q]
    __shared__ ulonglong2 PQ[17 * 16];   // [mp][q]: (P, Qv)
    __shared__ float2     Gp[16 * 258];  // [q][h] = (a*Gre, -a*Gim)
    const int tid = threadIdx.x;
    const size_t bd = blockIdx.x;

    {
        float s, c;
        sincospif((float)tid * (1.0f / 128.0f), &s, &c);
        twcs[tid] = pack2(c, s);
        ulonglong2 t; t.x = pack2(c, c); t.y = pack2(s, s);
        tw2[tid] = t;
    }
    ((float4*)Ys)[tid] = ((const float4*)(g_Y + bd * 512))[tid];
    __syncthreads();

    // PQ build: G = sum_mp P cos(mp h) + Qv sin(mp h)
    {
        int mp = tid >> 4, q = tid & 15;     // mp = 0..15
        float2 P, Qv;
        if (mp == 0) { P = Ys[q]; Qv = make_float2(0.0f, 0.0f); }
        else {
            float2 ym = Ys[mp * 16 + q], yn = Ys[(32 - mp) * 16 + q];
            P  = make_float2(ym.x + yn.x, ym.y + yn.y);
            Qv = make_float2(-(ym.y - yn.y), ym.x - yn.x);   // i*(Ym - Y-m)
        }
        ulonglong2 pq; pq.x = pack2(P.x, P.y); pq.y = pack2(Qv.x, Qv.y);
        PQ[mp * 16 + q] = pq;
    }
    if (tid < 16) {
        int q = tid;                         // mp = 16 (t = -16): Qv = -i*Y
        float2 y = Ys[16 * 16 + q];
        ulonglong2 pq; pq.x = pack2(y.x, y.y); pq.y = pack2(y.y, -y.x);
        PQ[16 * 16 + q] = pq;
    }
    __syncthreads();

    // Part 1: G build over 17 m'
    #pragma unroll 2
    for (int it = 0; it < 16; it++) {
        int task = tid + it * 256;
        int q = task & 15, h = task >> 4;
        u64 g = 0ull;
        #pragma unroll
        for (int mp = 0; mp <= 16; mp++) {
            ulonglong2 t  = tw2[(mp * h) & 255];
            ulonglong2 pq = PQ[mp * 16 + q];
            g = fma2(pq.x, t.x, g);
            g = fma2(pq.y, t.y, g);
        }
        float2 gv = unpack2(g);
        float a = (q == 0) ? (1.0f / 256.0f) : (2.0f / 256.0f);
        Gp[q * 258 + h] = make_float2(a * gv.x, -a * gv.y);
    }
    __syncthreads();

    // Part 2: out GEMM with w-symmetry
    const int w2 = tid & 127;
    const int hg = tid >> 7;
    u64 twc[16];
    #pragma unroll
    for (int q = 0; q < 16; q++) twc[q] = twcs[(q * w2) & 255];   // (cos, sin)

    float* ob = out + bd * 65536;
    const int h0 = hg * 128;
    #pragma unroll 2
    for (int hh = h0; hh < h0 + 128; hh += 2) {
        u64 c0 = 0ull, c1 = 0ull;
        #pragma unroll
        for (int q = 0; q < 16; q++) {
            ulonglong2 g = *(const ulonglong2*)&Gp[q * 258 + hh];  // broadcast
            c0 = fma2(g.x, twc[q], c0);
            c1 = fma2(g.y, twc[q], c1);
        }
        float2 r0 = unpack2(c0), r1 = unpack2(c1);
        ob[hh * 256 + w2]       = r0.x + r0.y;
        ob[(hh + 1) * 256 + w2] = r1.x + r1.y;
        if (w2) {
            ob[hh * 256 + 256 - w2]       = r0.x - r0.y;
            ob[(hh + 1) * 256 + 256 - w2] = r1.x - r1.y;
        }
    }
    // w = 128 column: cos(pi q) = (-1)^q, sin = 0
    {
        int h = tid;
        float acc = 0.0f;
        #pragma unroll
        for (int q = 0; q < 16; q++) {
            float v = Gp[q * 258 + h].x;
            acc += (q & 1) ? -v : v;
        }
        ob[h * 256 + 128] = acc;
    }
}

extern "C" void kernel_launch(void* const* d_in, const int* in_sizes, int n_in,
                              void* d_out, int out_size) {
    const float* x  = (const float*)d_in[0];
    const float* w1 = (const float*)d_in[1];
    const float* w2 = (const float*)d_in[2];
    float* out = (float*)d_out;

    const int SMEM_AB = 192640;
    const int SMEM_M  = 1024 * 8 + 4096 * 16;          // 73728
    cudaFuncSetAttribute(kAB, cudaFuncAttributeMaxDynamicSharedMemorySize, SMEM_AB);
    cudaFuncSetAttribute(kM,  cudaFuncAttributeMaxDynamicSharedMemorySize, SMEM_M);

    kAB<<<NBC, 256, SMEM_AB>>>(x);
    kM<<<512, 256, SMEM_M>>>(w1, w2);
    kCD<<<NBC, 256>>>(out);
}

// round 7
// speedup vs baseline: 1.6273x; 1.2892x over previous
#include <cuda_runtime.h>

// SpectralConv2d: B=16, C_IN=C_OUT=64, H=W=256, M=16
//  kAB (restructured): per (b,c):
//    phase 1 (h-DFT first, register-resident): for each w (=thread),
//      A_m'[w] = k*sum_h x[h,w] cos(m'th), B_m'[w] = k*sum_h x[h,w] sin(m'th),
//      m'=0..16, h-mirror pairs (127 iters), x read coalesced from global.
//    phase 2 (w-DFT on 17 m' rows, w-mirror): per (m',q):
//      Cc=Σ S_A cos, Cs=Σ D_A sin, Dc=Σ S_B cos, Ds=Σ D_B sin
//      X2[+m'] = (Cc-Ds) - i(Cs+Dc);  X2[-m'] = (Cc+Ds) + i(Dc-Cs)
//  kM : per-(m,q) complex channel mix [16x64]*[64x64]   (unchanged)
//  kCD: symmetric G build + symmetric inverse-w GEMM     (unchanged)

#define NBC   (16*64)       // 1024

typedef unsigned long long u64;

__device__ float2 g_X2[NBC * 32 * 16];     // [bc][m][q]
__device__ float2 g_Y [NBC * 32 * 16];     // [bd][m][q]

__device__ __forceinline__ u64 pack2(float lo, float hi) {
    u64 r; asm("mov.b64 %0, {%1,%2};" : "=l"(r) : "f"(lo), "f"(hi)); return r;
}
__device__ __forceinline__ float2 unpack2(u64 v) {
    float lo, hi; asm("mov.b64 {%0,%1}, %2;" : "=f"(lo), "=f"(hi) : "l"(v));
    return make_float2(lo, hi);
}
__device__ __forceinline__ u64 fma2(u64 a, u64 b, u64 c) {
    u64 d; asm("fma.rn.f32x2 %0, %1, %2, %3;" : "=l"(d) : "l"(a), "l"(b), "l"(c)); return d;
}
__device__ __forceinline__ u64 add2(u64 a, u64 b) {
    u64 d; asm("add.rn.f32x2 %0, %1, %2;" : "=l"(d) : "l"(a), "l"(b)); return d;
}

// ================= Fused stage A+B (h-first) =================
// smem (bytes):
//   tw1p : ulonglong2[256*8] @0      ((c2j,c2j+1)k,(s2j,s2j+1)k)   32768
//   tw16 : u64[256]          @32768  (c16,s16)*k                    2048
//   P    : u64[17*257]       @34816  [m'][w] = (A,B)  (pad->34960)
//   E2   : ulonglong2[129*16]@69776  ((c,c),(s,s)) for (wp,q)      33024
// total 102800 -> 2 CTAs/SM
__global__ __launch_bounds__(288, 2) void kAB(const float* __restrict__ x) {
    extern __shared__ char sm[];
    ulonglong2* tw1p = (ulonglong2*)sm;
    u64*        tw16 = (u64*)(sm + 32768);
    u64*        P    = (u64*)(sm + 34816);
    ulonglong2* E2   = (ulonglong2*)(sm + 69776);

    const int tid = threadIdx.x;
    const size_t bc = blockIdx.x;
    const float k = 1.0f / 256.0f;

    // build phase-1 twiddle tables (warps 0-7)
    if (tid < 256) {
        int h = tid;
        float cb[17], sb[17];
        #pragma unroll
        for (int m = 0; m < 17; m++) {
            float s, c;
            sincospif((float)((m * h) & 255) * (1.0f / 128.0f), &s, &c);
            cb[m] = c * k; sb[m] = s * k;
        }
        #pragma unroll
        for (int j = 0; j < 8; j++) {
            ulonglong2 v;
            v.x = pack2(cb[2 * j], cb[2 * j + 1]);
            v.y = pack2(sb[2 * j], sb[2 * j + 1]);
            tw1p[h * 8 + j] = v;
        }
        tw16[h] = pack2(cb[16], sb[16]);
    }
    __syncthreads();

    if (tid < 256) {
        // ---- phase 1: per-w register accumulation over h ----
        const int w = tid;
        const float* xb_ = x + bc * 65536;
        u64 accA[8], accB[8], acc16;

        float x0 = xb_[w], x128 = xb_[128 * 256 + w];
        float ve = (x0 + x128) * k, vo = (x0 - x128) * k;
        u64 pe = pack2(ve, vo);
        #pragma unroll
        for (int j = 0; j < 8; j++) { accA[j] = pe; accB[j] = 0ull; }
        acc16 = pack2(ve, 0.0f);

        const float* pa = xb_ + 256 + w;
        const float* pb = xb_ + 255 * 256 + w;
        #pragma unroll 2
        for (int h = 1; h <= 127; h++) {
            float xa = __ldg(pa), xv = __ldg(pb);
            pa += 256; pb -= 256;
            float s_ = xa + xv, d_ = xa - xv;
            u64 ss = pack2(s_, s_), dd = pack2(d_, d_);
            const ulonglong2* tp = &tw1p[h * 8];
            #pragma unroll
            for (int j = 0; j < 8; j++) {
                ulonglong2 t = tp[j];
                accA[j] = fma2(ss, t.x, accA[j]);
                accB[j] = fma2(dd, t.y, accB[j]);
            }
            acc16 = fma2(pack2(s_, d_), tw16[h], acc16);
        }

        #pragma unroll
        for (int j = 0; j < 8; j++) {
            float2 a = unpack2(accA[j]);
            float2 b = unpack2(accB[j]);
            P[(2 * j) * 257 + w]     = pack2(a.x, b.x);
            P[(2 * j + 1) * 257 + w] = pack2(a.y, b.y);
        }
        P[16 * 257 + w] = acc16;
    } else {
        // warp 8: build E2 table concurrently with phase 1
        int lt = tid - 256;
        for (int idx = lt; idx < 129 * 16; idx += 32) {
            int wp = idx >> 4, q = idx & 15;
            float s, c;
            sincospif((float)(q * wp) * (1.0f / 128.0f), &s, &c);
            ulonglong2 v; v.x = pack2(c, c); v.y = pack2(s, s);
            E2[idx] = v;
        }
    }
    __syncthreads();

    // ---- phase 2: w-DFT on 17 m' rows (w-mirror), task = (m', q) ----
    if (tid < 272) {
        const int mp = tid >> 4, q = tid & 15;
        const u64* Pm = P + mp * 257;
        const u64 NEG1 = pack2(-1.0f, -1.0f);

        float sq = (q & 1) ? -1.0f : 1.0f;
        u64 acc1 = fma2(Pm[128], pack2(sq, sq), Pm[0]);   // (Cc, Dc)
        u64 acc2 = 0ull;                                   // (Cs, Ds)

        #pragma unroll 2
        for (int wp = 1; wp <= 127; wp++) {
            u64 Pa = Pm[wp];
            u64 Pb = Pm[256 - wp];
            u64 S = add2(Pa, Pb);
            u64 D = fma2(Pb, NEG1, Pa);
            ulonglong2 e = E2[wp * 16 + q];
            acc1 = fma2(S, e.x, acc1);
            acc2 = fma2(D, e.y, acc2);
        }
        float2 r1 = unpack2(acc1);   // (Cc, Dc)
        float2 r2 = unpack2(acc2);   // (Cs, Ds)
        float2* dst = g_X2 + bc * 512;
        if (mp <= 15) dst[mp * 16 + q]        = make_float2(r1.x - r2.y, -(r2.x + r1.y));
        if (mp >= 1)  dst[(32 - mp) * 16 + q] = make_float2(r1.x + r2.y, r1.y - r2.x);
    }
}

// ================= Channel mixing (unchanged) =================
__global__ __launch_bounds__(256) void kM(const float* __restrict__ w1,
                                          const float* __restrict__ w2) {
    extern __shared__ char smM[];
    float2* Xs = (float2*)smM;                       // [b*64+c]
    ulonglong2* Wpk = (ulonglong2*)(smM + 1024 * 8); // [c*64+d] = ((wr,wi),(-wi,wr))
    const int tid = threadIdx.x;
    const int m = blockIdx.x >> 4;
    const int q = blockIdx.x & 15;
    const float* wsrc = (m < 16) ? w1 : w2;
    const int t_w = (m < 16) ? m : (m - 16);

    for (int i = tid; i < 1024; i += 256) {
        int b = i >> 6, c = i & 63;
        Xs[i] = g_X2[((size_t)(b * 64 + c) * 32 + m) * 16 + q];
    }
    for (int i = tid; i < 4096; i += 256) {
        int c = i >> 6, d = i & 63;
        const float* p = wsrc + ((size_t)(d * 64 + c) * 256 + t_w * 16 + q) * 2;
        float wr = p[0], wi = p[1];
        ulonglong2 v; v.x = pack2(wr, wi); v.y = pack2(-wi, wr);
        Wpk[c * 64 + d] = v;
    }
    __syncthreads();

    const int b = tid >> 4;
    const int dl = tid & 15;
    u64 accA[4], accB[4];
    #pragma unroll
    for (int j = 0; j < 4; j++) { accA[j] = 0ull; accB[j] = 0ull; }

    #pragma unroll 4
    for (int c = 0; c < 64; c++) {
        float2 xv = Xs[b * 64 + c];
        u64 xr = pack2(xv.x, xv.x), xi = pack2(xv.y, xv.y);
        #pragma unroll
        for (int j = 0; j < 4; j++) {
            ulonglong2 wv = Wpk[c * 64 + dl + 16 * j];
            accA[j] = fma2(xr, wv.x, accA[j]);
            accB[j] = fma2(xi, wv.y, accB[j]);
        }
    }
    #pragma unroll
    for (int j = 0; j < 4; j++) {
        int d = dl + 16 * j;
        float2 ra = unpack2(accA[j]), rb = unpack2(accB[j]);
        g_Y[((size_t)(b * 64 + d) * 32 + m) * 16 + q] =
            make_float2(ra.x + rb.x, ra.y + rb.y);
    }
}

// ================= Inverse: symmetric G build + symmetric w-GEMM =================
__global__ __launch_bounds__(256) void kCD(float* __restrict__ out) {
    __shared__ u64        twcs[256];     // (c, s)
    __shared__ ulonglong2 tw2[256];      // ((c,c),(s,s))
    __shared__ float2     Ys[512];       // [m][q]
    __shared__ ulonglong2 PQ[17 * 16];   // [mp][q]: (P, Qv)
    __shared__ float2     Gp[16 * 258];  // [q][h] = (a*Gre, -a*Gim)
    const int tid = threadIdx.x;
    const size_t bd = blockIdx.x;

    {
        float s, c;
        sincospif((float)tid * (1.0f / 128.0f), &s, &c);
        twcs[tid] = pack2(c, s);
        ulonglong2 t; t.x = pack2(c, c); t.y = pack2(s, s);
        tw2[tid] = t;
    }
    ((float4*)Ys)[tid] = ((const float4*)(g_Y + bd * 512))[tid];
    __syncthreads();

    {
        int mp = tid >> 4, q = tid & 15;     // mp = 0..15
        float2 Pv, Qv;
        if (mp == 0) { Pv = Ys[q]; Qv = make_float2(0.0f, 0.0f); }
        else {
            float2 ym = Ys[mp * 16 + q], yn = Ys[(32 - mp) * 16 + q];
            Pv = make_float2(ym.x + yn.x, ym.y + yn.y);
            Qv = make_float2(-(ym.y - yn.y), ym.x - yn.x);   // i*(Ym - Y-m)
        }
        ulonglong2 pq; pq.x = pack2(Pv.x, Pv.y); pq.y = pack2(Qv.x, Qv.y);
        PQ[mp * 16 + q] = pq;
    }
    if (tid < 16) {
        int q = tid;                         // mp = 16 (t = -16): Qv = -i*Y
        float2 y = Ys[16 * 16 + q];
        ulonglong2 pq; pq.x = pack2(y.x, y.y); pq.y = pack2(y.y, -y.x);
        PQ[16 * 16 + q] = pq;
    }
    __syncthreads();

    #pragma unroll 2
    for (int it = 0; it < 16; it++) {
        int task = tid + it * 256;
        int q = task & 15, h = task >> 4;
        u64 g = 0ull;
        #pragma unroll
        for (int mp = 0; mp <= 16; mp++) {
            ulonglong2 t  = tw2[(mp * h) & 255];
            ulonglong2 pq = PQ[mp * 16 + q];
            g = fma2(pq.x, t.x, g);
            g = fma2(pq.y, t.y, g);
        }
        float2 gv = unpack2(g);
        float a = (q == 0) ? (1.0f / 256.0f) : (2.0f / 256.0f);
        Gp[q * 258 + h] = make_float2(a * gv.x, -a * gv.y);
    }
    __syncthreads();

    const int w2 = tid & 127;
    const int hg = tid >> 7;
    u64 twc[16];
    #pragma unroll
    for (int q = 0; q < 16; q++) twc[q] = twcs[(q * w2) & 255];   // (cos, sin)

    float* ob = out + bd * 65536;
    const int h0 = hg * 128;
    #pragma unroll 2
    for (int hh = h0; hh < h0 + 128; hh += 2) {
        u64 c0 = 0ull, c1 = 0ull;
        #pragma unroll
        for (int q = 0; q < 16; q++) {
            ulonglong2 g = *(const ulonglong2*)&Gp[q * 258 + hh];  // broadcast
            c0 = fma2(g.x, twc[q], c0);
            c1 = fma2(g.y, twc[q], c1);
        }
        float2 r0 = unpack2(c0), r1 = unpack2(c1);
        ob[hh * 256 + w2]       = r0.x + r0.y;
        ob[(hh + 1) * 256 + w2] = r1.x + r1.y;
        if (w2) {
            ob[hh * 256 + 256 - w2]       = r0.x - r0.y;
            ob[(hh + 1) * 256 + 256 - w2] = r1.x - r1.y;
        }
    }
    {
        int h = tid;
        float acc = 0.0f;
        #pragma unroll
        for (int q = 0; q < 16; q++) {
            float v = Gp[q * 258 + h].x;
            acc += (q & 1) ? -v : v;
        }
        ob[h * 256 + 128] = acc;
    }
}

extern "C" void kernel_launch(void* const* d_in, const int* in_sizes, int n_in,
                              void* d_out, int out_size) {
    const float* x  = (const float*)d_in[0];
    const float* w1 = (const float*)d_in[1];
    const float* w2 = (const float*)d_in[2];
    float* out = (float*)d_out;

    const int SMEM_AB = 102800;
    const int SMEM_M  = 1024 * 8 + 4096 * 16;          // 73728
    cudaFuncSetAttribute(kAB, cudaFuncAttributeMaxDynamicSharedMemorySize, SMEM_AB);
    cudaFuncSetAttribute(kM,  cudaFuncAttributeMaxDynamicSharedMemorySize, SMEM_M);

    kAB<<<NBC, 288, SMEM_AB>>>(x);
    kM<<<512, 256, SMEM_M>>>(w1, w2);
    kCD<<<NBC, 256>>>(out);
}

// round 11
// speedup vs baseline: 2.0637x; 1.2682x over previous
#include <cuda_runtime.h>

// SpectralConv2d: B=16, C_IN=C_OUT=64, H=W=256, M=16
//  kAB: per (b,c), h-first pruned DFT with cp.async double-buffered x streaming.
//    phase 1: thread=w; accumulate A_m'=k*sum_h x cos, B_m'=k*sum_h x sin
//             (m'=0..16) over h-mirror pairs, x staged via LDGSTS chunks.
//    phase 2: w-DFT on 17 m' rows with w-mirror symmetry -> X2[+-m'].
//  kM : per-(m,q) complex channel mix [16x64]*[64x64].
//  kCD: symmetric G build + symmetric inverse-w GEMM.

#define NBC   (16*64)       // 1024

typedef unsigned long long u64;

__device__ float2 g_X2[NBC * 32 * 16];     // [bc][m][q]
__device__ float2 g_Y [NBC * 32 * 16];     // [bd][m][q]

__device__ __forceinline__ u64 pack2(float lo, float hi) {
    u64 r; asm("mov.b64 %0, {%1,%2};" : "=l"(r) : "f"(lo), "f"(hi)); return r;
}
__device__ __forceinline__ float2 unpack2(u64 v) {
    float lo, hi; asm("mov.b64 {%0,%1}, %2;" : "=f"(lo), "=f"(hi) : "l"(v));
    return make_float2(lo, hi);
}
__device__ __forceinline__ u64 fma2(u64 a, u64 b, u64 c) {
    u64 d; asm("fma.rn.f32x2 %0, %1, %2, %3;" : "=l"(d) : "l"(a), "l"(b), "l"(c)); return d;
}
__device__ __forceinline__ u64 add2(u64 a, u64 b) {
    u64 d; asm("add.rn.f32x2 %0, %1, %2;" : "=l"(d) : "l"(a), "l"(b)); return d;
}
__device__ __forceinline__ void cp_async16(unsigned smem_addr, const void* gptr) {
    asm volatile("cp.async.cg.shared.global [%0], [%1], 16;"
                 :: "r"(smem_addr), "l"(gptr));
}
__device__ __forceinline__ void cp_commit() {
    asm volatile("cp.async.commit_group;");
}
template <int N>
__device__ __forceinline__ void cp_wait() {
    asm volatile("cp.async.wait_group %0;" :: "n"(N));
}

// ================= Fused stage A+B (h-first, cp.async streamed) =================
// smem (bytes):
//   tw1p : ulonglong2[256*8] @0      ((c2j,c2j+1)k,(s2j,s2j+1)k)   32768
//   tw16 : u64[256]          @32768  (c16,s16)*k                    2048
//   P    : u64[17*257]       @34816  [m'][w] = (A,B)                34960
//   union @69776 (33024):  xbuf float[2][16][256] (32768)  |  E2 ulonglong2[129*16]
// total 102800 -> 2 CTAs/SM
__global__ __launch_bounds__(288, 2) void kAB(const float* __restrict__ x) {
    extern __shared__ char sm[];
    ulonglong2* tw1p = (ulonglong2*)sm;
    u64*        tw16 = (u64*)(sm + 32768);
    u64*        P    = (u64*)(sm + 34816);
    float*      xbuf = (float*)(sm + 69776);      // [2][16 rows][256]
    ulonglong2* E2   = (ulonglong2*)(sm + 69776); // phase-2 alias

    const int tid = threadIdx.x;
    const size_t bc = blockIdx.x;
    const float k = 1.0f / 256.0f;
    const float* xb_ = x + bc * 65536;
    const unsigned xbuf_base = (unsigned)__cvta_generic_to_shared(xbuf);

    // kick off chunk 0 copy first (pairs p=1..7: lo rows 1..7, hi rows 255..249)
    {
        const int pstart = 1, n = 7;
        for (int idx = tid; idx < n * 64; idx += 288) {
            int i = idx >> 6, col = idx & 63;
            cp_async16(xbuf_base + i * 1024 + col * 16,
                       xb_ + (pstart + i) * 256 + col * 4);
            cp_async16(xbuf_base + 8192 + i * 1024 + col * 16,
                       xb_ + (256 - (pstart + i)) * 256 + col * 4);
        }
        cp_commit();
    }

    // phase-1 twiddle tables (warps 0-7)
    if (tid < 256) {
        int h = tid;
        float cb[17], sb[17];
        #pragma unroll
        for (int m = 0; m < 17; m++) {
            float s, c;
            sincospif((float)((m * h) & 255) * (1.0f / 128.0f), &s, &c);
            cb[m] = c * k; sb[m] = s * k;
        }
        #pragma unroll
        for (int j = 0; j < 8; j++) {
            ulonglong2 v;
            v.x = pack2(cb[2 * j], cb[2 * j + 1]);
            v.y = pack2(sb[2 * j], sb[2 * j + 1]);
            tw1p[h * 8 + j] = v;
        }
        tw16[h] = pack2(cb[16], sb[16]);
    }

    // special pair (0,128): direct loads, latency hidden behind table build
    u64 accA[8], accB[8], acc16;
    float x0 = 0.0f, x128 = 0.0f;
    if (tid < 256) { x0 = xb_[tid]; x128 = xb_[32768 + tid]; }

    __syncthreads();    // tw tables visible

    if (tid < 256) {
        float ve = (x0 + x128) * k, vo = (x0 - x128) * k;
        u64 pe = pack2(ve, vo);
        #pragma unroll
        for (int j = 0; j < 8; j++) { accA[j] = pe; accB[j] = 0ull; }
        acc16 = pack2(ve, 0.0f);
    }

    const int w = tid;   // valid when tid<256

    #pragma unroll 1
    for (int c = 0; c < 16; c++) {
        // issue next chunk's copy, then wait for current
        if (c < 15) {
            const int ps = 8 * (c + 1);
            const unsigned dst = xbuf_base + ((c + 1) & 1) * 16384;
            for (int idx = tid; idx < 8 * 64; idx += 288) {
                int i = idx >> 6, col = idx & 63;
                cp_async16(dst + i * 1024 + col * 16,
                           xb_ + (ps + i) * 256 + col * 4);
                cp_async16(dst + 8192 + i * 1024 + col * 16,
                           xb_ + (256 - (ps + i)) * 256 + col * 4);
            }
            cp_commit();
            cp_wait<1>();
        } else {
            cp_wait<0>();
        }
        __syncthreads();   // buffer c ready for all

        if (tid < 256) {
            const int pstart = c ? 8 * c : 1;
            const int n = c ? 8 : 7;
            const float* xlo = xbuf + (c & 1) * 4096;
            const float* xhi = xlo + 2048;
            #pragma unroll 2
            for (int i = 0; i < n; i++) {
                int p = pstart + i;
                float xa = xlo[i * 256 + w];
                float xv = xhi[i * 256 + w];
                float s_ = xa + xv, d_ = xa - xv;
                u64 ss = pack2(s_, s_), dd = pack2(d_, d_);
                const ulonglong2* tp = &tw1p[p * 8];
                #pragma unroll
                for (int j = 0; j < 8; j++) {
                    ulonglong2 t = tp[j];
                    accA[j] = fma2(ss, t.x, accA[j]);
                    accB[j] = fma2(dd, t.y, accB[j]);
                }
                acc16 = fma2(pack2(s_, d_), tw16[p], acc16);
            }
        }
        __syncthreads();   // compute done before buffer reuse
    }

    // write P, build E2 (xbuf now dead)
    if (tid < 256) {
        #pragma unroll
        for (int j = 0; j < 8; j++) {
            float2 a = unpack2(accA[j]);
            float2 b = unpack2(accB[j]);
            P[(2 * j) * 257 + w]     = pack2(a.x, b.x);
            P[(2 * j + 1) * 257 + w] = pack2(a.y, b.y);
        }
        P[16 * 257 + w] = acc16;
    }
    for (int idx = tid; idx < 129 * 16; idx += 288) {
        int wp = idx >> 4, q = idx & 15;
        float s, c;
        sincospif((float)(q * wp) * (1.0f / 128.0f), &s, &c);
        ulonglong2 v; v.x = pack2(c, c); v.y = pack2(s, s);
        E2[idx] = v;
    }
    __syncthreads();

    // ---- phase 2: w-DFT on 17 m' rows (w-mirror), task = (m', q) ----
    if (tid < 272) {
        const int mp = tid >> 4, q = tid & 15;
        const u64* Pm = P + mp * 257;
        const u64 NEG1 = pack2(-1.0f, -1.0f);

        float sq = (q & 1) ? -1.0f : 1.0f;
        u64 acc1 = fma2(Pm[128], pack2(sq, sq), Pm[0]);   // (Cc, Dc)
        u64 acc2 = 0ull;                                   // (Cs, Ds)

        #pragma unroll 2
        for (int wp = 1; wp <= 127; wp++) {
            u64 Pa = Pm[wp];
            u64 Pb = Pm[256 - wp];
            u64 S = add2(Pa, Pb);
            u64 D = fma2(Pb, NEG1, Pa);
            ulonglong2 e = E2[wp * 16 + q];
            acc1 = fma2(S, e.x, acc1);
            acc2 = fma2(D, e.y, acc2);
        }
        float2 r1 = unpack2(acc1);   // (Cc, Dc)
        float2 r2 = unpack2(acc2);   // (Cs, Ds)
        float2* dst = g_X2 + bc * 512;
        if (mp <= 15) dst[mp * 16 + q]        = make_float2(r1.x - r2.y, -(r2.x + r1.y));
        if (mp >= 1)  dst[(32 - mp) * 16 + q] = make_float2(r1.x + r2.y, r1.y - r2.x);
    }
}

// ================= Channel mixing (unchanged) =================
__global__ __launch_bounds__(256) void kM(const float* __restrict__ w1,
                                          const float* __restrict__ w2) {
    extern __shared__ char smM[];
    float2* Xs = (float2*)smM;                       // [b*64+c]
    ulonglong2* Wpk = (ulonglong2*)(smM + 1024 * 8); // [c*64+d] = ((wr,wi),(-wi,wr))
    const int tid = threadIdx.x;
    const int m = blockIdx.x >> 4;
    const int q = blockIdx.x & 15;
    const float* wsrc = (m < 16) ? w1 : w2;
    const int t_w = (m < 16) ? m : (m - 16);

    for (int i = tid; i < 1024; i += 256) {
        int b = i >> 6, c = i & 63;
        Xs[i] = g_X2[((size_t)(b * 64 + c) * 32 + m) * 16 + q];
    }
    for (int i = tid; i < 4096; i += 256) {
        int c = i >> 6, d = i & 63;
        const float* p = wsrc + ((size_t)(d * 64 + c) * 256 + t_w * 16 + q) * 2;
        float wr = p[0], wi = p[1];
        ulonglong2 v; v.x = pack2(wr, wi); v.y = pack2(-wi, wr);
        Wpk[c * 64 + d] = v;
    }
    __syncthreads();

    const int b = tid >> 4;
    const int dl = tid & 15;
    u64 accA[4], accB[4];
    #pragma unroll
    for (int j = 0; j < 4; j++) { accA[j] = 0ull; accB[j] = 0ull; }

    #pragma unroll 4
    for (int c = 0; c < 64; c++) {
        float2 xv = Xs[b * 64 + c];
        u64 xr = pack2(xv.x, xv.x), xi = pack2(xv.y, xv.y);
        #pragma unroll
        for (int j = 0; j < 4; j++) {
            ulonglong2 wv = Wpk[c * 64 + dl + 16 * j];
            accA[j] = fma2(xr, wv.x, accA[j]);
            accB[j] = fma2(xi, wv.y, accB[j]);
        }
    }
    #pragma unroll
    for (int j = 0; j < 4; j++) {
        int d = dl + 16 * j;
        float2 ra = unpack2(accA[j]), rb = unpack2(accB[j]);
        g_Y[((size_t)(b * 64 + d) * 32 + m) * 16 + q] =
            make_float2(ra.x + rb.x, ra.y + rb.y);
    }
}

// ================= Inverse: symmetric G build + symmetric w-GEMM =================
__global__ __launch_bounds__(256) void kCD(float* __restrict__ out) {
    __shared__ u64        twcs[256];     // (c, s)
    __shared__ ulonglong2 tw2[256];      // ((c,c),(s,s))
    __shared__ float2     Ys[512];       // [m][q]
    __shared__ ulonglong2 PQ[17 * 16];   // [mp][q]: (P, Qv)
    __shared__ float2     Gp[16 * 258];  // [q][h] = (a*Gre, -a*Gim)
    const int tid = threadIdx.x;
    const size_t bd = blockIdx.x;

    {
        float s, c;
        sincospif((float)tid * (1.0f / 128.0f), &s, &c);
        twcs[tid] = pack2(c, s);
        ulonglong2 t; t.x = pack2(c, c); t.y = pack2(s, s);
        tw2[tid] = t;
    }
    ((float4*)Ys)[tid] = ((const float4*)(g_Y + bd * 512))[tid];
    __syncthreads();

    {
        int mp = tid >> 4, q = tid & 15;     // mp = 0..15
        float2 Pv, Qv;
        if (mp == 0) { Pv = Ys[q]; Qv = make_float2(0.0f, 0.0f); }
        else {
            float2 ym = Ys[mp * 16 + q], yn = Ys[(32 - mp) * 16 + q];
            Pv = make_float2(ym.x + yn.x, ym.y + yn.y);
            Qv = make_float2(-(ym.y - yn.y), ym.x - yn.x);   // i*(Ym - Y-m)
        }
        ulonglong2 pq; pq.x = pack2(Pv.x, Pv.y); pq.y = pack2(Qv.x, Qv.y);
        PQ[mp * 16 + q] = pq;
    }
    if (tid < 16) {
        int q = tid;                         // mp = 16 (t = -16): Qv = -i*Y
        float2 y = Ys[16 * 16 + q];
        ulonglong2 pq; pq.x = pack2(y.x, y.y); pq.y = pack2(y.y, -y.x);
        PQ[16 * 16 + q] = pq;
    }
    __syncthreads();

    #pragma unroll 2
    for (int it = 0; it < 16; it++) {
        int task = tid + it * 256;
        int q = task & 15, h = task >> 4;
        u64 g = 0ull;
        #pragma unroll
        for (int mp = 0; mp <= 16; mp++) {
            ulonglong2 t  = tw2[(mp * h) & 255];
            ulonglong2 pq = PQ[mp * 16 + q];
            g = fma2(pq.x, t.x, g);
            g = fma2(pq.y, t.y, g);
        }
        float2 gv = unpack2(g);
        float a = (q == 0) ? (1.0f / 256.0f) : (2.0f / 256.0f);
        Gp[q * 258 + h] = make_float2(a * gv.x, -a * gv.y);
    }
    __syncthreads();

    const int w2 = tid & 127;
    const int hg = tid >> 7;
    u64 twc[16];
    #pragma unroll
    for (int q = 0; q < 16; q++) twc[q] = twcs[(q * w2) & 255];   // (cos, sin)

    float* ob = out + bd * 65536;
    const int h0 = hg * 128;
    #pragma unroll 2
    for (int hh = h0; hh < h0 + 128; hh += 2) {
        u64 c0 = 0ull, c1 = 0ull;
        #pragma unroll
        for (int q = 0; q < 16; q++) {
            ulonglong2 g = *(const ulonglong2*)&Gp[q * 258 + hh];  // broadcast
            c0 = fma2(g.x, twc[q], c0);
            c1 = fma2(g.y, twc[q], c1);
        }
        float2 r0 = unpack2(c0), r1 = unpack2(c1);
        ob[hh * 256 + w2]       = r0.x + r0.y;
        ob[(hh + 1) * 256 + w2] = r1.x + r1.y;
        if (w2) {
            ob[hh * 256 + 256 - w2]       = r0.x - r0.y;
            ob[(hh + 1) * 256 + 256 - w2] = r1.x - r1.y;
        }
    }
    {
        int h = tid;
        float acc = 0.0f;
        #pragma unroll
        for (int q = 0; q < 16; q++) {
            float v = Gp[q * 258 + h].x;
            acc += (q & 1) ? -v : v;
        }
        ob[h * 256 + 128] = acc;
    }
}

extern "C" void kernel_launch(void* const* d_in, const int* in_sizes, int n_in,
                              void* d_out, int out_size) {
    const float* x  = (const float*)d_in[0];
    const float* w1 = (const float*)d_in[1];
    const float* w2 = (const float*)d_in[2];
    float* out = (float*)d_out;

    const int SMEM_AB = 102800;
    const int SMEM_M  = 1024 * 8 + 4096 * 16;          // 73728
    cudaFuncSetAttribute(kAB, cudaFuncAttributeMaxDynamicSharedMemorySize, SMEM_AB);
    cudaFuncSetAttribute(kM,  cudaFuncAttributeMaxDynamicSharedMemorySize, SMEM_M);

    kAB<<<NBC, 288, SMEM_AB>>>(x);
    kM<<<512, 256, SMEM_M>>>(w1, w2);
    kCD<<<NBC, 256>>>(out);
}

// round 12
// speedup vs baseline: 2.2138x; 1.0728x over previous
#include <cuda_runtime.h>

// SpectralConv2d: B=16, C_IN=C_OUT=64, H=W=256, M=16
//  kAB: per (b,c), h-first pruned DFT; 2 w-columns per thread; cp.async
//       triple-buffered x streaming (1 barrier/chunk); phase 2 w-mirror DFT.
//  kM : per-(m,q) complex channel mix [16x64]*[64x64].
//  kCD: parity-shared G build (h, h+128) + 2-column symmetric inverse-w GEMM.

#define NBC   (16*64)       // 1024

typedef unsigned long long u64;

__device__ float2 g_X2[NBC * 32 * 16];     // [bc][m][q]
__device__ float2 g_Y [NBC * 32 * 16];     // [bd][m][q]

__device__ __forceinline__ u64 pack2(float lo, float hi) {
    u64 r; asm("mov.b64 %0, {%1,%2};" : "=l"(r) : "f"(lo), "f"(hi)); return r;
}
__device__ __forceinline__ float2 unpack2(u64 v) {
    float lo, hi; asm("mov.b64 {%0,%1}, %2;" : "=f"(lo), "=f"(hi) : "l"(v));
    return make_float2(lo, hi);
}
__device__ __forceinline__ u64 fma2(u64 a, u64 b, u64 c) {
    u64 d; asm("fma.rn.f32x2 %0, %1, %2, %3;" : "=l"(d) : "l"(a), "l"(b), "l"(c)); return d;
}
__device__ __forceinline__ u64 add2(u64 a, u64 b) {
    u64 d; asm("add.rn.f32x2 %0, %1, %2;" : "=l"(d) : "l"(a), "l"(b)); return d;
}
__device__ __forceinline__ void cp_async16(unsigned smem_addr, const void* gptr) {
    asm volatile("cp.async.cg.shared.global [%0], [%1], 16;"
                 :: "r"(smem_addr), "l"(gptr));
}
__device__ __forceinline__ void cp_commit() {
    asm volatile("cp.async.commit_group;");
}
template <int N>
__device__ __forceinline__ void cp_wait() {
    asm volatile("cp.async.wait_group %0;" :: "n"(N));
}

// ================= Fused stage A+B =================
// smem (bytes):
//   tw1p : ulonglong2[128*8] @0      ((c2j,c2j+1)k,(s2j,s2j+1)k)  16384
//   tw16 : u64[128]          @16384                                1024
//   P    : u64[17*257]       @17408  [m'][w] = (A,B)              34960
//   union @52368 (49152):  xbuf float[3][16][256]  |  E2 ulonglong2[129*16] (33024)
// total 101520 -> 2 CTAs/SM
__global__ __launch_bounds__(288, 2) void kAB(const float* __restrict__ x) {
    extern __shared__ char sm[];
    ulonglong2* tw1p = (ulonglong2*)sm;
    u64*        tw16 = (u64*)(sm + 16384);
    u64*        P    = (u64*)(sm + 17408);
    float*      xbuf = (float*)(sm + 52368);      // 3 bufs x 4096 floats
    ulonglong2* E2   = (ulonglong2*)(sm + 52368); // phase-2 alias

    const int tid = threadIdx.x;
    const size_t bc = blockIdx.x;
    const float k = 1.0f / 256.0f;
    const float* xb_ = x + bc * 65536;
    const unsigned xbuf_base = (unsigned)__cvta_generic_to_shared(xbuf);

    // copy-slot precompute: 512 slots (8 rows x 64 float4, lo+hi issued together)
    const int i0 = tid >> 6,  co0 = tid & 63;
    const int s1 = tid + 288;
    const int i1 = s1 >> 6,   co1 = s1 & 63;
    const float* glo0 = xb_ + i0 * 256 + co0 * 4;
    const float* ghi0 = xb_ + (256 - i0) * 256 + co0 * 4;
    const float* glo1 = xb_ + i1 * 256 + co1 * 4;
    const float* ghi1 = xb_ + (256 - i1) * 256 + co1 * 4;
    const unsigned so0 = (unsigned)(i0 * 1024 + co0 * 16);
    const unsigned so1 = (unsigned)(i1 * 1024 + co1 * 16);

    auto issue = [&](int c) {
        const int ps  = (c == 0) ? 1 : 8 * c;
        const int lim = ((c == 0) ? 7 : 8) * 64;
        const unsigned db = xbuf_base + (unsigned)((c % 3) * 16384);
        const int off = ps * 256;
        if (tid < lim) {
            cp_async16(db + so0,        glo0 + off);
            cp_async16(db + 8192 + so0, ghi0 - off);
        }
        if (s1 < lim) {
            cp_async16(db + so1,        glo1 + off);
            cp_async16(db + 8192 + so1, ghi1 - off);
        }
        cp_commit();
    };

    issue(0);
    issue(1);

    // phase-1 twiddle tables (h = 1..127 used; tid<128 builds)
    if (tid < 128) {
        int h = tid;
        float cb[17], sb[17];
        #pragma unroll
        for (int m = 0; m < 17; m++) {
            float s, c;
            sincospif((float)((m * h) & 255) * (1.0f / 128.0f), &s, &c);
            cb[m] = c * k; sb[m] = s * k;
        }
        #pragma unroll
        for (int j = 0; j < 8; j++) {
            ulonglong2 v;
            v.x = pack2(cb[2 * j], cb[2 * j + 1]);
            v.y = pack2(sb[2 * j], sb[2 * j + 1]);
            tw1p[h * 8 + j] = v;
        }
        tw16[h] = pack2(cb[16], sb[16]);
    }

    // special pair (0,128) loads for both columns
    float x0a = 0.f, x0b = 0.f, x1a = 0.f, x1b = 0.f;
    if (tid < 128) {
        x0a = xb_[tid];           x0b = xb_[tid + 128];
        x1a = xb_[32768 + tid];   x1b = xb_[32768 + tid + 128];
    }
    __syncthreads();

    u64 accA0[8], accB0[8], accA1[8], accB1[8], acc16a, acc16b;
    if (tid < 128) {
        float vea = (x0a + x1a) * k, voa = (x0a - x1a) * k;
        float veb = (x0b + x1b) * k, vob = (x0b - x1b) * k;
        u64 pea = pack2(vea, voa), peb = pack2(veb, vob);
        #pragma unroll
        for (int j = 0; j < 8; j++) {
            accA0[j] = pea; accB0[j] = 0ull;
            accA1[j] = peb; accB1[j] = 0ull;
        }
        acc16a = pack2(vea, 0.0f);
        acc16b = pack2(veb, 0.0f);
    }

    #pragma unroll 1
    for (int c = 0; c < 16; c++) {
        if (c == 15) { cp_wait<0>(); } else { cp_wait<1>(); }
        __syncthreads();                       // chunk c visible; chunk c-1 compute done
        if (c <= 13) issue(c + 2);             // overwrites buf[(c-1)%3] -- safe

        if (tid < 128) {
            const int pstart = c ? 8 * c : 1;
            const int n = c ? 8 : 7;
            const float* xlo = xbuf + (c % 3) * 4096;
            const float* xhi = xlo + 2048;
            #pragma unroll 2
            for (int i = 0; i < n; i++) {
                int p = pstart + i;
                float xa0 = xlo[i * 256 + tid], xa1 = xlo[i * 256 + tid + 128];
                float xv0 = xhi[i * 256 + tid], xv1 = xhi[i * 256 + tid + 128];
                float sA = xa0 + xv0, dA = xa0 - xv0;
                float sB = xa1 + xv1, dB = xa1 - xv1;
                u64 ss0 = pack2(sA, sA), dd0 = pack2(dA, dA);
                u64 ss1 = pack2(sB, sB), dd1 = pack2(dB, dB);
                const ulonglong2* tp = &tw1p[p * 8];
                #pragma unroll
                for (int j = 0; j < 8; j++) {
                    ulonglong2 t = tp[j];
                    accA0[j] = fma2(ss0, t.x, accA0[j]);
                    accB0[j] = fma2(dd0, t.y, accB0[j]);
                    accA1[j] = fma2(ss1, t.x, accA1[j]);
                    accB1[j] = fma2(dd1, t.y, accB1[j]);
                }
                u64 t16 = tw16[p];
                acc16a = fma2(pack2(sA, dA), t16, acc16a);
                acc16b = fma2(pack2(sB, dB), t16, acc16b);
            }
        }
    }
    __syncthreads();   // final compute done before E2 overwrites xbuf

    if (tid < 128) {
        #pragma unroll
        for (int j = 0; j < 8; j++) {
            float2 a0 = unpack2(accA0[j]), b0 = unpack2(accB0[j]);
            float2 a1 = unpack2(accA1[j]), b1 = unpack2(accB1[j]);
            P[(2 * j) * 257 + tid]           = pack2(a0.x, b0.x);
            P[(2 * j + 1) * 257 + tid]       = pack2(a0.y, b0.y);
            P[(2 * j) * 257 + tid + 128]     = pack2(a1.x, b1.x);
            P[(2 * j + 1) * 257 + tid + 128] = pack2(a1.y, b1.y);
        }
        P[16 * 257 + tid]       = acc16a;
        P[16 * 257 + tid + 128] = acc16b;
    }
    for (int idx = tid; idx < 129 * 16; idx += 288) {
        int wp = idx >> 4, q = idx & 15;
        float s, c;
        sincospif((float)(q * wp) * (1.0f / 128.0f), &s, &c);
        ulonglong2 v; v.x = pack2(c, c); v.y = pack2(s, s);
        E2[idx] = v;
    }
    __syncthreads();

    // ---- phase 2: w-DFT on 17 m' rows (w-mirror), task = (m', q) ----
    if (tid < 272) {
        const int mp = tid >> 4, q = tid & 15;
        const u64* Pm = P + mp * 257;
        const u64 NEG1 = pack2(-1.0f, -1.0f);

        float sq = (q & 1) ? -1.0f : 1.0f;
        u64 acc1 = fma2(Pm[128], pack2(sq, sq), Pm[0]);   // (Cc, Dc)
        u64 acc2 = 0ull;                                   // (Cs, Ds)

        #pragma unroll 2
        for (int wp = 1; wp <= 127; wp++) {
            u64 Pa = Pm[wp];
            u64 Pb = Pm[256 - wp];
            u64 S = add2(Pa, Pb);
            u64 D = fma2(Pb, NEG1, Pa);
            ulonglong2 e = E2[wp * 16 + q];
            acc1 = fma2(S, e.x, acc1);
            acc2 = fma2(D, e.y, acc2);
        }
        float2 r1 = unpack2(acc1);   // (Cc, Dc)
        float2 r2 = unpack2(acc2);   // (Cs, Ds)
        float2* dst = g_X2 + bc * 512;
        if (mp <= 15) dst[mp * 16 + q]        = make_float2(r1.x - r2.y, -(r2.x + r1.y));
        if (mp >= 1)  dst[(32 - mp) * 16 + q] = make_float2(r1.x + r2.y, r1.y - r2.x);
    }
}

// ================= Channel mixing (unchanged) =================
__global__ __launch_bounds__(256) void kM(const float* __restrict__ w1,
                                          const float* __restrict__ w2) {
    extern __shared__ char smM[];
    float2* Xs = (float2*)smM;                       // [b*64+c]
    ulonglong2* Wpk = (ulonglong2*)(smM + 1024 * 8); // [c*64+d] = ((wr,wi),(-wi,wr))
    const int tid = threadIdx.x;
    const int m = blockIdx.x >> 4;
    const int q = blockIdx.x & 15;
    const float* wsrc = (m < 16) ? w1 : w2;
    const int t_w = (m < 16) ? m : (m - 16);

    for (int i = tid; i < 1024; i += 256) {
        int b = i >> 6, c = i & 63;
        Xs[i] = g_X2[((size_t)(b * 64 + c) * 32 + m) * 16 + q];
    }
    for (int i = tid; i < 4096; i += 256) {
        int c = i >> 6, d = i & 63;
        const float* p = wsrc + ((size_t)(d * 64 + c) * 256 + t_w * 16 + q) * 2;
        float wr = p[0], wi = p[1];
        ulonglong2 v; v.x = pack2(wr, wi); v.y = pack2(-wi, wr);
        Wpk[c * 64 + d] = v;
    }
    __syncthreads();

    const int b = tid >> 4;
    const int dl = tid & 15;
    u64 accA[4], accB[4];
    #pragma unroll
    for (int j = 0; j < 4; j++) { accA[j] = 0ull; accB[j] = 0ull; }

    #pragma unroll 4
    for (int c = 0; c < 64; c++) {
        float2 xv = Xs[b * 64 + c];
        u64 xr = pack2(xv.x, xv.x), xi = pack2(xv.y, xv.y);
        #pragma unroll
        for (int j = 0; j < 4; j++) {
            ulonglong2 wv = Wpk[c * 64 + dl + 16 * j];
            accA[j] = fma2(xr, wv.x, accA[j]);
            accB[j] = fma2(xi, wv.y, accB[j]);
        }
    }
    #pragma unroll
    for (int j = 0; j < 4; j++) {
        int d = dl + 16 * j;
        float2 ra = unpack2(accA[j]), rb = unpack2(accB[j]);
        g_Y[((size_t)(b * 64 + d) * 32 + m) * 16 + q] =
            make_float2(ra.x + rb.x, ra.y + rb.y);
    }
}

// ================= Inverse: parity-shared G build + 2-col symmetric w-GEMM ======
__global__ __launch_bounds__(256) void kCD(float* __restrict__ out) {
    __shared__ u64        twcs[256];     // (c, s)
    __shared__ ulonglong2 tw2[256];      // ((c,c),(s,s))
    __shared__ float2     Ys[512];       // [m][q]
    __shared__ ulonglong2 PQ[17 * 16];   // [mp][q]: (P, Qv)
    __shared__ float2     Gp[16 * 258];  // [q][h] = (a*Gre, -a*Gim)
    const int tid = threadIdx.x;
    const size_t bd = blockIdx.x;

    {
        float s, c;
        sincospif((float)tid * (1.0f / 128.0f), &s, &c);
        twcs[tid] = pack2(c, s);
        ulonglong2 t; t.x = pack2(c, c); t.y = pack2(s, s);
        tw2[tid] = t;
    }
    ((float4*)Ys)[tid] = ((const float4*)(g_Y + bd * 512))[tid];
    __syncthreads();

    {
        int mp = tid >> 4, q = tid & 15;     // mp = 0..15
        float2 Pv, Qv;
        if (mp == 0) { Pv = Ys[q]; Qv = make_float2(0.0f, 0.0f); }
        else {
            float2 ym = Ys[mp * 16 + q], yn = Ys[(32 - mp) * 16 + q];
            Pv = make_float2(ym.x + yn.x, ym.y + yn.y);
            Qv = make_float2(-(ym.y - yn.y), ym.x - yn.x);   // i*(Ym - Y-m)
        }
        ulonglong2 pq; pq.x = pack2(Pv.x, Pv.y); pq.y = pack2(Qv.x, Qv.y);
        PQ[mp * 16 + q] = pq;
    }
    if (tid < 16) {
        int q = tid;                         // mp = 16 (t = -16): Qv = -i*Y
        float2 y = Ys[16 * 16 + q];
        ulonglong2 pq; pq.x = pack2(y.x, y.y); pq.y = pack2(y.y, -y.x);
        PQ[16 * 16 + q] = pq;
    }
    __syncthreads();

    // Part 1: rows h0 and h0+128 share twiddles via parity of mp
    const u64 NEG1 = pack2(-1.0f, -1.0f);
    #pragma unroll 2
    for (int it = 0; it < 8; it++) {
        int task = tid + it * 256;           // 2048 = 128 h0 x 16 q
        int q = task & 15, h0 = task >> 4;
        u64 Se = 0ull, So = 0ull;
        #pragma unroll
        for (int mp = 0; mp <= 16; mp++) {
            ulonglong2 t  = tw2[(mp * h0) & 255];
            ulonglong2 pq = PQ[mp * 16 + q];
            if (mp & 1) { So = fma2(pq.x, t.x, So); So = fma2(pq.y, t.y, So); }
            else        { Se = fma2(pq.x, t.x, Se); Se = fma2(pq.y, t.y, Se); }
        }
        float a = (q == 0) ? (1.0f / 256.0f) : (2.0f / 256.0f);
        float2 v0 = unpack2(add2(Se, So));
        float2 v1 = unpack2(fma2(So, NEG1, Se));
        Gp[q * 258 + h0]       = make_float2(a * v0.x, -a * v0.y);
        Gp[q * 258 + h0 + 128] = make_float2(a * v1.x, -a * v1.y);
    }
    __syncthreads();

    // Part 2: 2 w' columns per thread, 4 h-groups
    const int wa = tid & 63;
    const int wb = wa + 64;
    const int hg = tid >> 6;
    u64 twa[16], twb[16];
    #pragma unroll
    for (int q = 0; q < 16; q++) {
        twa[q] = twcs[(q * wa) & 255];
        twb[q] = twcs[(q * wb) & 255];
    }

    float* ob = out + bd * 65536;
    const int hbase = hg * 64;
    #pragma unroll 2
    for (int hh = hbase; hh < hbase + 64; hh += 2) {
        u64 ca0 = 0ull, ca1 = 0ull, cb0 = 0ull, cb1 = 0ull;
        #pragma unroll
        for (int q = 0; q < 16; q++) {
            ulonglong2 g = *(const ulonglong2*)&Gp[q * 258 + hh];  // broadcast
            ca0 = fma2(g.x, twa[q], ca0);
            ca1 = fma2(g.y, twa[q], ca1);
            cb0 = fma2(g.x, twb[q], cb0);
            cb1 = fma2(g.y, twb[q], cb1);
        }
        float2 ra0 = unpack2(ca0), ra1 = unpack2(ca1);
        float2 rb0 = unpack2(cb0), rb1 = unpack2(cb1);
        ob[hh * 256 + wa]             = ra0.x + ra0.y;
        ob[(hh + 1) * 256 + wa]       = ra1.x + ra1.y;
        ob[hh * 256 + wb]             = rb0.x + rb0.y;
        ob[(hh + 1) * 256 + wb]       = rb1.x + rb1.y;
        ob[hh * 256 + 256 - wb]       = rb0.x - rb0.y;
        ob[(hh + 1) * 256 + 256 - wb] = rb1.x - rb1.y;
        if (wa) {
            ob[hh * 256 + 256 - wa]       = ra0.x - ra0.y;
            ob[(hh + 1) * 256 + 256 - wa] = ra1.x - ra1.y;
        }
    }
    // w = 128 column: cos(pi q) = (-1)^q, sin = 0
    {
        int h = tid;
        float acc = 0.0f;
        #pragma unroll
        for (int q = 0; q < 16; q++) {
            float v = Gp[q * 258 + h].x;
            acc += (q & 1) ? -v : v;
        }
        ob[h * 256 + 128] = acc;
    }
}

extern "C" void kernel_launch(void* const* d_in, const int* in_sizes, int n_in,
                              void* d_out, int out_size) {
    const float* x  = (const float*)d_in[0];
    const float* w1 = (const float*)d_in[1];
    const float* w2 = (const float*)d_in[2];
    float* out = (float*)d_out;

    const int SMEM_AB = 101520;
    const int SMEM_M  = 1024 * 8 + 4096 * 16;          // 73728
    cudaFuncSetAttribute(kAB, cudaFuncAttributeMaxDynamicSharedMemorySize, SMEM_AB);
    cudaFuncSetAttribute(kM,  cudaFuncAttributeMaxDynamicSharedMemorySize, SMEM_M);

    kAB<<<NBC, 288, SMEM_AB>>>(x);
    kM<<<512, 256, SMEM_M>>>(w1, w2);
    kCD<<<NBC, 256>>>(out);
}

// round 13
// speedup vs baseline: 2.2881x; 1.0335x over previous
#include <cuda_runtime.h>

// SpectralConv2d: B=16, C_IN=C_OUT=64, H=W=256, M=16
//  kAB: per (b,c), h-first pruned DFT; cp.async triple-buffered streaming;
//       PHASE-ALIASED smem (phase1: twiddles+xbuf | phase2: P+E2) -> 3 CTAs/SM.
//  kM : per-(m,q) complex channel mix [16x64]*[64x64].
//  kCD: parity-shared G build (h, h+128) + 2-column symmetric inverse-w GEMM.

#define NBC   (16*64)       // 1024

typedef unsigned long long u64;

__device__ float2 g_X2[NBC * 32 * 16];     // [bc][m][q]
__device__ float2 g_Y [NBC * 32 * 16];     // [bd][m][q]

__device__ __forceinline__ u64 pack2(float lo, float hi) {
    u64 r; asm("mov.b64 %0, {%1,%2};" : "=l"(r) : "f"(lo), "f"(hi)); return r;
}
__device__ __forceinline__ float2 unpack2(u64 v) {
    float lo, hi; asm("mov.b64 {%0,%1}, %2;" : "=f"(lo), "=f"(hi) : "l"(v));
    return make_float2(lo, hi);
}
__device__ __forceinline__ u64 fma2(u64 a, u64 b, u64 c) {
    u64 d; asm("fma.rn.f32x2 %0, %1, %2, %3;" : "=l"(d) : "l"(a), "l"(b), "l"(c)); return d;
}
__device__ __forceinline__ u64 add2(u64 a, u64 b) {
    u64 d; asm("add.rn.f32x2 %0, %1, %2;" : "=l"(d) : "l"(a), "l"(b)); return d;
}
__device__ __forceinline__ void cp_async16(unsigned smem_addr, const void* gptr) {
    asm volatile("cp.async.cg.shared.global [%0], [%1], 16;"
                 :: "r"(smem_addr), "l"(gptr));
}
__device__ __forceinline__ void cp_commit() {
    asm volatile("cp.async.commit_group;");
}
template <int N>
__device__ __forceinline__ void cp_wait() {
    asm volatile("cp.async.wait_group %0;" :: "n"(N));
}

// ================= Fused stage A+B (phase-aliased smem) =================
// phase 1: tw1p ulonglong2[128*8] @0 (16384) | tw16 u64[128] @16384 (1024)
//          xbuf float[3][16][256] @17408 (49152)  -> end 66560
// phase 2: P u64[17*257] @0 (34952, pad 34960) | E2 ulonglong2[129*16] @34960 (33024)
//          -> end 67984
// smem = 67984 -> 3 CTAs/SM
__global__ __launch_bounds__(256, 3) void kAB(const float* __restrict__ x) {
    extern __shared__ char sm[];
    ulonglong2* tw1p = (ulonglong2*)sm;
    u64*        tw16 = (u64*)(sm + 16384);
    float*      xbuf = (float*)(sm + 17408);
    u64*        P    = (u64*)sm;                   // phase-2 alias
    ulonglong2* E2   = (ulonglong2*)(sm + 34960);  // phase-2 alias

    const int tid = threadIdx.x;
    const size_t bc = blockIdx.x;
    const float k = 1.0f / 256.0f;
    const float* xb_ = x + bc * 65536;
    const unsigned xbuf_base = (unsigned)__cvta_generic_to_shared(xbuf);

    // copy-slot addressing: slot tid (rows 0..3) and tid+256 (rows 4..7)
    const int i0 = tid >> 6, co0 = tid & 63;
    const float* glo0 = xb_ + i0 * 256 + co0 * 4;
    const float* ghi0 = xb_ + (256 - i0) * 256 + co0 * 4;
    const unsigned so0 = (unsigned)(i0 * 1024 + co0 * 16);

    auto issue = [&](int c) {
        const int ps = c ? 8 * c : 1;
        const int nslots = (c ? 8 : 7) * 64;
        const unsigned db = xbuf_base + (unsigned)((c % 3) * 16384);
        const int off = ps * 256;
        if (tid < nslots) {
            cp_async16(db + so0,        glo0 + off);
            cp_async16(db + 8192 + so0, ghi0 - off);
        }
        if (tid + 256 < nslots) {
            cp_async16(db + so0 + 4096,        glo0 + 1024 + off);
            cp_async16(db + 8192 + so0 + 4096, ghi0 - 1024 - off);
        }
        cp_commit();
    };

    issue(0);
    issue(1);

    // phase-1 twiddle tables (h = 1..127; tid<128 builds)
    if (tid < 128) {
        int h = tid;
        float cb[17], sb[17];
        #pragma unroll
        for (int m = 0; m < 17; m++) {
            float s, c;
            sincospif((float)((m * h) & 255) * (1.0f / 128.0f), &s, &c);
            cb[m] = c * k; sb[m] = s * k;
        }
        #pragma unroll
        for (int j = 0; j < 8; j++) {
            ulonglong2 v;
            v.x = pack2(cb[2 * j], cb[2 * j + 1]);
            v.y = pack2(sb[2 * j], sb[2 * j + 1]);
            tw1p[h * 8 + j] = v;
        }
        tw16[h] = pack2(cb[16], sb[16]);
    }

    // special pair (0,128)
    const int w = tid;
    float x0 = xb_[w], x128 = xb_[32768 + w];
    __syncthreads();    // tw tables visible

    u64 accA[8], accB[8], acc16;
    {
        float ve = (x0 + x128) * k, vo = (x0 - x128) * k;
        u64 pe = pack2(ve, vo);
        #pragma unroll
        for (int j = 0; j < 8; j++) { accA[j] = pe; accB[j] = 0ull; }
        acc16 = pack2(ve, 0.0f);
    }

    #pragma unroll 1
    for (int c = 0; c < 16; c++) {
        if (c == 15) { cp_wait<0>(); } else { cp_wait<1>(); }
        __syncthreads();                       // chunk c visible; chunk c-1 compute done
        if (c <= 13) issue(c + 2);             // overwrites buf[(c-1)%3] -- safe

        const int pstart = c ? 8 * c : 1;
        const int n = c ? 8 : 7;
        const float* xlo = xbuf + (c % 3) * 4096;
        const float* xhi = xlo + 2048;
        #pragma unroll 2
        for (int i = 0; i < n; i++) {
            int p = pstart + i;
            float xa = xlo[i * 256 + w];
            float xv = xhi[i * 256 + w];
            float s_ = xa + xv, d_ = xa - xv;
            u64 ss = pack2(s_, s_), dd = pack2(d_, d_);
            const ulonglong2* tp = &tw1p[p * 8];
            #pragma unroll
            for (int j = 0; j < 8; j++) {
                ulonglong2 t = tp[j];
                accA[j] = fma2(ss, t.x, accA[j]);
                accB[j] = fma2(dd, t.y, accB[j]);
            }
            acc16 = fma2(pack2(s_, d_), tw16[p], acc16);
        }
    }
    __syncthreads();   // all compute + twiddle reads done before P/E2 overwrite

    // write P (overwrites tw region) and build E2 (over xbuf region)
    #pragma unroll
    for (int j = 0; j < 8; j++) {
        float2 a = unpack2(accA[j]);
        float2 b = unpack2(accB[j]);
        P[(2 * j) * 257 + w]     = pack2(a.x, b.x);
        P[(2 * j + 1) * 257 + w] = pack2(a.y, b.y);
    }
    P[16 * 257 + w] = acc16;
    for (int idx = tid; idx < 129 * 16; idx += 256) {
        int wp = idx >> 4, q = idx & 15;
        float s, c;
        sincospif((float)(q * wp) * (1.0f / 128.0f), &s, &c);
        ulonglong2 v; v.x = pack2(c, c); v.y = pack2(s, s);
        E2[idx] = v;
    }
    __syncthreads();

    // ---- phase 2: w-DFT on 17 m' rows (w-mirror), task = (m', q) ----
    for (int task = tid; task < 272; task += 256) {
        const int mp = task >> 4, q = task & 15;
        const u64* Pm = P + mp * 257;
        const u64 NEG1 = pack2(-1.0f, -1.0f);

        float sq = (q & 1) ? -1.0f : 1.0f;
        u64 acc1 = fma2(Pm[128], pack2(sq, sq), Pm[0]);   // (Cc, Dc)
        u64 acc2 = 0ull;                                   // (Cs, Ds)

        #pragma unroll 2
        for (int wp = 1; wp <= 127; wp++) {
            u64 Pa = Pm[wp];
            u64 Pb = Pm[256 - wp];
            u64 S = add2(Pa, Pb);
            u64 D = fma2(Pb, NEG1, Pa);
            ulonglong2 e = E2[wp * 16 + q];
            acc1 = fma2(S, e.x, acc1);
            acc2 = fma2(D, e.y, acc2);
        }
        float2 r1 = unpack2(acc1);   // (Cc, Dc)
        float2 r2 = unpack2(acc2);   // (Cs, Ds)
        float2* dst = g_X2 + bc * 512;
        if (mp <= 15) dst[mp * 16 + q]        = make_float2(r1.x - r2.y, -(r2.x + r1.y));
        if (mp >= 1)  dst[(32 - mp) * 16 + q] = make_float2(r1.x + r2.y, r1.y - r2.x);
    }
}

// ================= Channel mixing (unchanged) =================
__global__ __launch_bounds__(256) void kM(const float* __restrict__ w1,
                                          const float* __restrict__ w2) {
    extern __shared__ char smM[];
    float2* Xs = (float2*)smM;                       // [b*64+c]
    ulonglong2* Wpk = (ulonglong2*)(smM + 1024 * 8); // [c*64+d] = ((wr,wi),(-wi,wr))
    const int tid = threadIdx.x;
    const int m = blockIdx.x >> 4;
    const int q = blockIdx.x & 15;
    const float* wsrc = (m < 16) ? w1 : w2;
    const int t_w = (m < 16) ? m : (m - 16);

    for (int i = tid; i < 1024; i += 256) {
        int b = i >> 6, c = i & 63;
        Xs[i] = g_X2[((size_t)(b * 64 + c) * 32 + m) * 16 + q];
    }
    for (int i = tid; i < 4096; i += 256) {
        int c = i >> 6, d = i & 63;
        const float* p = wsrc + ((size_t)(d * 64 + c) * 256 + t_w * 16 + q) * 2;
        float wr = p[0], wi = p[1];
        ulonglong2 v; v.x = pack2(wr, wi); v.y = pack2(-wi, wr);
        Wpk[c * 64 + d] = v;
    }
    __syncthreads();

    const int b = tid >> 4;
    const int dl = tid & 15;
    u64 accA[4], accB[4];
    #pragma unroll
    for (int j = 0; j < 4; j++) { accA[j] = 0ull; accB[j] = 0ull; }

    #pragma unroll 4
    for (int c = 0; c < 64; c++) {
        float2 xv = Xs[b * 64 + c];
        u64 xr = pack2(xv.x, xv.x), xi = pack2(xv.y, xv.y);
        #pragma unroll
        for (int j = 0; j < 4; j++) {
            ulonglong2 wv = Wpk[c * 64 + dl + 16 * j];
            accA[j] = fma2(xr, wv.x, accA[j]);
            accB[j] = fma2(xi, wv.y, accB[j]);
        }
    }
    #pragma unroll
    for (int j = 0; j < 4; j++) {
        int d = dl + 16 * j;
        float2 ra = unpack2(accA[j]), rb = unpack2(accB[j]);
        g_Y[((size_t)(b * 64 + d) * 32 + m) * 16 + q] =
            make_float2(ra.x + rb.x, ra.y + rb.y);
    }
}

// ================= Inverse: parity-shared G build + 2-col symmetric w-GEMM ======
__global__ __launch_bounds__(256) void kCD(float* __restrict__ out) {
    __shared__ u64        twcs[256];     // (c, s)
    __shared__ ulonglong2 tw2[256];      // ((c,c),(s,s))
    __shared__ float2     Ys[512];       // [m][q]
    __shared__ ulonglong2 PQ[17 * 16];   // [mp][q]: (P, Qv)
    __shared__ float2     Gp[16 * 258];  // [q][h] = (a*Gre, -a*Gim)
    const int tid = threadIdx.x;
    const size_t bd = blockIdx.x;

    {
        float s, c;
        sincospif((float)tid * (1.0f / 128.0f), &s, &c);
        twcs[tid] = pack2(c, s);
        ulonglong2 t; t.x = pack2(c, c); t.y = pack2(s, s);
        tw2[tid] = t;
    }
    ((float4*)Ys)[tid] = ((const float4*)(g_Y + bd * 512))[tid];
    __syncthreads();

    {
        int mp = tid >> 4, q = tid & 15;     // mp = 0..15
        float2 Pv, Qv;
        if (mp == 0) { Pv = Ys[q]; Qv = make_float2(0.0f, 0.0f); }
        else {
            float2 ym = Ys[mp * 16 + q], yn = Ys[(32 - mp) * 16 + q];
            Pv = make_float2(ym.x + yn.x, ym.y + yn.y);
            Qv = make_float2(-(ym.y - yn.y), ym.x - yn.x);   // i*(Ym - Y-m)
        }
        ulonglong2 pq; pq.x = pack2(Pv.x, Pv.y); pq.y = pack2(Qv.x, Qv.y);
        PQ[mp * 16 + q] = pq;
    }
    if (tid < 16) {
        int q = tid;                         // mp = 16 (t = -16): Qv = -i*Y
        float2 y = Ys[16 * 16 + q];
        ulonglong2 pq; pq.x = pack2(y.x, y.y); pq.y = pack2(y.y, -y.x);
        PQ[16 * 16 + q] = pq;
    }
    __syncthreads();

    // Part 1: rows h0 and h0+128 share twiddles via parity of mp
    const u64 NEG1 = pack2(-1.0f, -1.0f);
    #pragma unroll 2
    for (int it = 0; it < 8; it++) {
        int task = tid + it * 256;           // 2048 = 128 h0 x 16 q
        int q = task & 15, h0 = task >> 4;
        u64 Se = 0ull, So = 0ull;
        #pragma unroll
        for (int mp = 0; mp <= 16; mp++) {
            ulonglong2 t  = tw2[(mp * h0) & 255];
            ulonglong2 pq = PQ[mp * 16 + q];
            if (mp & 1) { So = fma2(pq.x, t.x, So); So = fma2(pq.y, t.y, So); }
            else        { Se = fma2(pq.x, t.x, Se); Se = fma2(pq.y, t.y, Se); }
        }
        float a = (q == 0) ? (1.0f / 256.0f) : (2.0f / 256.0f);
        float2 v0 = unpack2(add2(Se, So));
        float2 v1 = unpack2(fma2(So, NEG1, Se));
        Gp[q * 258 + h0]       = make_float2(a * v0.x, -a * v0.y);
        Gp[q * 258 + h0 + 128] = make_float2(a * v1.x, -a * v1.y);
    }
    __syncthreads();

    // Part 2: 2 w' columns per thread, 4 h-groups
    const int wa = tid & 63;
    const int wb = wa + 64;
    const int hg = tid >> 6;
    u64 twa[16], twb[16];
    #pragma unroll
    for (int q = 0; q < 16; q++) {
        twa[q] = twcs[(q * wa) & 255];
        twb[q] = twcs[(q * wb) & 255];
    }

    float* ob = out + bd * 65536;
    const int hbase = hg * 64;
    #pragma unroll 2
    for (int hh = hbase; hh < hbase + 64; hh += 2) {
        u64 ca0 = 0ull, ca1 = 0ull, cb0 = 0ull, cb1 = 0ull;
        #pragma unroll
        for (int q = 0; q < 16; q++) {
            ulonglong2 g = *(const ulonglong2*)&Gp[q * 258 + hh];  // broadcast
            ca0 = fma2(g.x, twa[q], ca0);
            ca1 = fma2(g.y, twa[q], ca1);
            cb0 = fma2(g.x, twb[q], cb0);
            cb1 = fma2(g.y, twb[q], cb1);
        }
        float2 ra0 = unpack2(ca0), ra1 = unpack2(ca1);
        float2 rb0 = unpack2(cb0), rb1 = unpack2(cb1);
        ob[hh * 256 + wa]             = ra0.x + ra0.y;
        ob[(hh + 1) * 256 + wa]       = ra1.x + ra1.y;
        ob[hh * 256 + wb]             = rb0.x + rb0.y;
        ob[(hh + 1) * 256 + wb]       = rb1.x + rb1.y;
        ob[hh * 256 + 256 - wb]       = rb0.x - rb0.y;
        ob[(hh + 1) * 256 + 256 - wb] = rb1.x - rb1.y;
        if (wa) {
            ob[hh * 256 + 256 - wa]       = ra0.x - ra0.y;
            ob[(hh + 1) * 256 + 256 - wa] = ra1.x - ra1.y;
        }
    }
    // w = 128 column: cos(pi q) = (-1)^q, sin = 0
    {
        int h = tid;
        float acc = 0.0f;
        #pragma unroll
        for (int q = 0; q < 16; q++) {
            float v = Gp[q * 258 + h].x;
            acc += (q & 1) ? -v : v;
        }
        ob[h * 256 + 128] = acc;
    }
}

extern "C" void kernel_launch(void* const* d_in, const int* in_sizes, int n_in,
                              void* d_out, int out_size) {
    const float* x  = (const float*)d_in[0];
    const float* w1 = (const float*)d_in[1];
    const float* w2 = (const float*)d_in[2];
    float* out = (float*)d_out;

    const int SMEM_AB = 67984;
    const int SMEM_M  = 1024 * 8 + 4096 * 16;          // 73728
    cudaFuncSetAttribute(kAB, cudaFuncAttributeMaxDynamicSharedMemorySize, SMEM_AB);
    cudaFuncSetAttribute(kM,  cudaFuncAttributeMaxDynamicSharedMemorySize, SMEM_M);

    kAB<<<NBC, 256, SMEM_AB>>>(x);
    kM<<<512, 256, SMEM_M>>>(w1, w2);
    kCD<<<NBC, 256>>>(out);
}

// round 14
// speedup vs baseline: 2.4679x; 1.0786x over previous
#include <cuda_runtime.h>

// SpectralConv2d: B=16, C_IN=C_OUT=64, H=W=256, M=16
//  kAB: per (b,c), h-first pruned DFT with QUARTET symmetry:
//       rows {h, 256-h, 128-h, 128+h}, m-parity-split accumulators ->
//       half the fma2 and half the twiddle LDS of the pair version.
//       cp.async triple-buffered (16 uniform chunks x 16 rows);
//       phase-aliased smem (p1: tables+xbuf | p2: P+E2) -> 3 CTAs/SM.
//  kM : per-(m,q) complex channel mix [16x64]*[64x64].
//  kCD: parity-shared G build (h, h+128) + 2-column symmetric inverse-w GEMM.

#define NBC   (16*64)       // 1024

typedef unsigned long long u64;

__device__ float2 g_X2[NBC * 32 * 16];     // [bc][m][q]
__device__ float2 g_Y [NBC * 32 * 16];     // [bd][m][q]

__device__ __forceinline__ u64 pack2(float lo, float hi) {
    u64 r; asm("mov.b64 %0, {%1,%2};" : "=l"(r) : "f"(lo), "f"(hi)); return r;
}
__device__ __forceinline__ float2 unpack2(u64 v) {
    float lo, hi; asm("mov.b64 {%0,%1}, %2;" : "=f"(lo), "=f"(hi) : "l"(v));
    return make_float2(lo, hi);
}
__device__ __forceinline__ u64 fma2(u64 a, u64 b, u64 c) {
    u64 d; asm("fma.rn.f32x2 %0, %1, %2, %3;" : "=l"(d) : "l"(a), "l"(b), "l"(c)); return d;
}
__device__ __forceinline__ u64 add2(u64 a, u64 b) {
    u64 d; asm("add.rn.f32x2 %0, %1, %2;" : "=l"(d) : "l"(a), "l"(b)); return d;
}
__device__ __forceinline__ void cp_async16(unsigned smem_addr, const void* gptr) {
    asm volatile("cp.async.cg.shared.global [%0], [%1], 16;"
                 :: "r"(smem_addr), "l"(gptr));
}
__device__ __forceinline__ void cp_commit() {
    asm volatile("cp.async.commit_group;");
}
template <int N>
__device__ __forceinline__ void cp_wait() {
    asm volatile("cp.async.wait_group %0;" :: "n"(N));
}

// ================= Fused stage A+B (quartet symmetry, phase-aliased smem) ======
// phase 1 (bytes):
//   twE  ulonglong2[65*4] @0     (4160)   even m pairs (4j,4j+2): (cos,cos),(sin,sin)
//   twO  ulonglong2[65*4] @4160  (4160)   odd  m pairs (4j+1,4j+3)
//   tw16 u64[65]          @8320  (520->pad 8848)   (c16,s16)*sc
//   xbuf float[3][16][256] @8848 (49152) -> end 58000
// phase 2:
//   P  u64[17*257] @0 (34952 -> pad 34960) | E2 ulonglong2[129*16] @34960 (33024)
// smem = 67984 -> 3 CTAs/SM
__global__ __launch_bounds__(256, 3) void kAB(const float* __restrict__ x) {
    extern __shared__ char sm[];
    ulonglong2* twE  = (ulonglong2*)sm;
    ulonglong2* twO  = (ulonglong2*)(sm + 4160);
    u64*        tw16 = (u64*)(sm + 8320);
    float*      xbuf = (float*)(sm + 8848);
    u64*        P    = (u64*)sm;                   // phase-2 alias
    ulonglong2* E2   = (ulonglong2*)(sm + 34960);  // phase-2 alias

    const int tid = threadIdx.x;
    const size_t bc = blockIdx.x;
    const float k = 1.0f / 256.0f;
    const float* xb_ = x + bc * 65536;
    const unsigned xbuf_base = (unsigned)__cvta_generic_to_shared(xbuf);

    // copy addressing: i0 = quartet-in-chunk, col = float4 column
    const int i0 = tid >> 6, col = tid & 63;
    const float* gA = xb_ + (1 + i0) * 256 + col * 4;     // row h        (+1024/chunk)
    const float* gB = xb_ + (255 - i0) * 256 + col * 4;   // row 256-h    (-1024/chunk)
    const float* gC = xb_ + (127 - i0) * 256 + col * 4;   // row 128-h    (-1024/chunk)
    const float* gD = xb_ + (129 + i0) * 256 + col * 4;   // row 128+h    (+1024/chunk)
    const unsigned sA = (unsigned)(i0 * 1024 + col * 16);

    auto issue = [&](int c) {
        const unsigned db = xbuf_base + (unsigned)((c % 3) * 16384);
        const int off = 1024 * c;
        cp_async16(db + sA,         gA + off);
        cp_async16(db + sA + 4096,  gB - off);
        cp_async16(db + sA + 8192,  gC - off);
        cp_async16(db + sA + 12288, gD + off);
        cp_commit();
    };

    issue(0);
    issue(1);

    // twiddle tables: h = 1..64 (h=64 scaled by 0.5 -> degenerate quartet correct)
    if (tid < 64) {
        int h = tid + 1;
        float sc = (h == 64) ? (0.5f * k) : k;
        float cb[17], sb[17];
        #pragma unroll
        for (int m = 0; m < 17; m++) {
            float s, c;
            sincospif((float)((m * h) & 255) * (1.0f / 128.0f), &s, &c);
            cb[m] = c * sc; sb[m] = s * sc;
        }
        #pragma unroll
        for (int j = 0; j < 4; j++) {
            ulonglong2 ve, vo;
            ve.x = pack2(cb[4 * j], cb[4 * j + 2]);
            ve.y = pack2(sb[4 * j], sb[4 * j + 2]);
            vo.x = pack2(cb[4 * j + 1], cb[4 * j + 3]);
            vo.y = pack2(sb[4 * j + 1], sb[4 * j + 3]);
            twE[h * 4 + j] = ve;
            twO[h * 4 + j] = vo;
        }
        tw16[h] = pack2(cb[16], sb[16]);
    }

    // special rows 0 and 128
    const int w = tid;
    float x0 = xb_[w], x128 = xb_[32768 + w];
    __syncthreads();    // tables visible

    // accumulators: evens (A,B for m=4j,4j+2), odds (m=4j+1,4j+3), m=16
    u64 accEA[4], accEB[4], accOA[4], accOB[4], acc16;
    {
        float ve = (x0 + x128) * k, vo = (x0 - x128) * k;
        u64 pe = pack2(ve, ve), po = pack2(vo, vo);
        #pragma unroll
        for (int j = 0; j < 4; j++) {
            accEA[j] = pe; accEB[j] = 0ull;
            accOA[j] = po; accOB[j] = 0ull;
        }
        acc16 = pack2(ve, 0.0f);
    }

    #pragma unroll 1
    for (int c = 0; c < 16; c++) {
        if (c == 15) { cp_wait<0>(); } else { cp_wait<1>(); }
        __syncthreads();                       // chunk c visible; chunk c-1 compute done
        if (c <= 13) issue(c + 2);

        const float* buf = xbuf + (c % 3) * 4096;
        const int hb = 4 * c + 1;
        #pragma unroll
        for (int i = 0; i < 4; i++) {
            float xa = buf[i * 256 + w];
            float xv = buf[1024 + i * 256 + w];
            float xc = buf[2048 + i * 256 + w];
            float xd = buf[3072 + i * 256 + w];
            float s_ = xa + xv, d_ = xa - xv;
            float s2 = xc + xd, d2 = xc - xd;
            float se = s_ + s2, so = s_ - s2;
            float de = d_ - d2, dO = d_ + d2;
            u64 sse = pack2(se, se), sso = pack2(so, so);
            u64 dde = pack2(de, de), ddo = pack2(dO, dO);
            const int ht = hb + i;
            const ulonglong2* tE = &twE[ht * 4];
            const ulonglong2* tO = &twO[ht * 4];
            #pragma unroll
            for (int j = 0; j < 4; j++) {
                ulonglong2 e = tE[j];
                ulonglong2 o = tO[j];
                accEA[j] = fma2(sse, e.x, accEA[j]);
                accEB[j] = fma2(dde, e.y, accEB[j]);
                accOA[j] = fma2(sso, o.x, accOA[j]);
                accOB[j] = fma2(ddo, o.y, accOB[j]);
            }
            acc16 = fma2(pack2(se, de), tw16[ht], acc16);
        }
    }
    __syncthreads();   // all compute + table reads done before P/E2 overwrite

    // write P[m][w] = (A_m, B_m)
    #pragma unroll
    for (int j = 0; j < 4; j++) {
        float2 aE = unpack2(accEA[j]), bE = unpack2(accEB[j]);
        float2 aO = unpack2(accOA[j]), bO = unpack2(accOB[j]);
        P[(4 * j) * 257 + w]     = pack2(aE.x, bE.x);
        P[(4 * j + 2) * 257 + w] = pack2(aE.y, bE.y);
        P[(4 * j + 1) * 257 + w] = pack2(aO.x, bO.x);
        P[(4 * j + 3) * 257 + w] = pack2(aO.y, bO.y);
    }
    P[16 * 257 + w] = acc16;
    for (int idx = tid; idx < 129 * 16; idx += 256) {
        int wp = idx >> 4, q = idx & 15;
        float s, c;
        sincospif((float)(q * wp) * (1.0f / 128.0f), &s, &c);
        ulonglong2 v; v.x = pack2(c, c); v.y = pack2(s, s);
        E2[idx] = v;
    }
    __syncthreads();

    // ---- phase 2: w-DFT on 17 m' rows (w-mirror), task = (m', q) ----
    for (int task = tid; task < 272; task += 256) {
        const int mp = task >> 4, q = task & 15;
        const u64* Pm = P + mp * 257;
        const u64 NEG1 = pack2(-1.0f, -1.0f);

        float sq = (q & 1) ? -1.0f : 1.0f;
        u64 acc1 = fma2(Pm[128], pack2(sq, sq), Pm[0]);   // (Cc, Dc)
        u64 acc2 = 0ull;                                   // (Cs, Ds)

        #pragma unroll 2
        for (int wp = 1; wp <= 127; wp++) {
            u64 Pa = Pm[wp];
            u64 Pb = Pm[256 - wp];
            u64 S = add2(Pa, Pb);
            u64 D = fma2(Pb, NEG1, Pa);
            ulonglong2 e = E2[wp * 16 + q];
            acc1 = fma2(S, e.x, acc1);
            acc2 = fma2(D, e.y, acc2);
        }
        float2 r1 = unpack2(acc1);   // (Cc, Dc)
        float2 r2 = unpack2(acc2);   // (Cs, Ds)
        float2* dst = g_X2 + bc * 512;
        if (mp <= 15) dst[mp * 16 + q]        = make_float2(r1.x - r2.y, -(r2.x + r1.y));
        if (mp >= 1)  dst[(32 - mp) * 16 + q] = make_float2(r1.x + r2.y, r1.y - r2.x);
    }
}

// ================= Channel mixing (unchanged) =================
__global__ __launch_bounds__(256) void kM(const float* __restrict__ w1,
                                          const float* __restrict__ w2) {
    extern __shared__ char smM[];
    float2* Xs = (float2*)smM;                       // [b*64+c]
    ulonglong2* Wpk = (ulonglong2*)(smM + 1024 * 8); // [c*64+d] = ((wr,wi),(-wi,wr))
    const int tid = threadIdx.x;
    const int m = blockIdx.x >> 4;
    const int q = blockIdx.x & 15;
    const float* wsrc = (m < 16) ? w1 : w2;
    const int t_w = (m < 16) ? m : (m - 16);

    for (int i = tid; i < 1024; i += 256) {
        int b = i >> 6, c = i & 63;
        Xs[i] = g_X2[((size_t)(b * 64 + c) * 32 + m) * 16 + q];
    }
    for (int i = tid; i < 4096; i += 256) {
        int c = i >> 6, d = i & 63;
        const float* p = wsrc + ((size_t)(d * 64 + c) * 256 + t_w * 16 + q) * 2;
        float wr = p[0], wi = p[1];
        ulonglong2 v; v.x = pack2(wr, wi); v.y = pack2(-wi, wr);
        Wpk[c * 64 + d] = v;
    }
    __syncthreads();

    const int b = tid >> 4;
    const int dl = tid & 15;
    u64 accA[4], accB[4];
    #pragma unroll
    for (int j = 0; j < 4; j++) { accA[j] = 0ull; accB[j] = 0ull; }

    #pragma unroll 4
    for (int c = 0; c < 64; c++) {
        float2 xv = Xs[b * 64 + c];
        u64 xr = pack2(xv.x, xv.x), xi = pack2(xv.y, xv.y);
        #pragma unroll
        for (int j = 0; j < 4; j++) {
            ulonglong2 wv = Wpk[c * 64 + dl + 16 * j];
            accA[j] = fma2(xr, wv.x, accA[j]);
            accB[j] = fma2(xi, wv.y, accB[j]);
        }
    }
    #pragma unroll
    for (int j = 0; j < 4; j++) {
        int d = dl + 16 * j;
        float2 ra = unpack2(accA[j]), rb = unpack2(accB[j]);
        g_Y[((size_t)(b * 64 + d) * 32 + m) * 16 + q] =
            make_float2(ra.x + rb.x, ra.y + rb.y);
    }
}

// ================= Inverse: parity-shared G build + 2-col symmetric w-GEMM ======
__global__ __launch_bounds__(256) void kCD(float* __restrict__ out) {
    __shared__ u64        twcs[256];     // (c, s)
    __shared__ ulonglong2 tw2[256];      // ((c,c),(s,s))
    __shared__ float2     Ys[512];       // [m][q]
    __shared__ ulonglong2 PQ[17 * 16];   // [mp][q]: (P, Qv)
    __shared__ float2     Gp[16 * 258];  // [q][h] = (a*Gre, -a*Gim)
    const int tid = threadIdx.x;
    const size_t bd = blockIdx.x;

    {
        float s, c;
        sincospif((float)tid * (1.0f / 128.0f), &s, &c);
        twcs[tid] = pack2(c, s);
        ulonglong2 t; t.x = pack2(c, c); t.y = pack2(s, s);
        tw2[tid] = t;
    }
    ((float4*)Ys)[tid] = ((const float4*)(g_Y + bd * 512))[tid];
    __syncthreads();

    {
        int mp = tid >> 4, q = tid & 15;     // mp = 0..15
        float2 Pv, Qv;
        if (mp == 0) { Pv = Ys[q]; Qv = make_float2(0.0f, 0.0f); }
        else {
            float2 ym = Ys[mp * 16 + q], yn = Ys[(32 - mp) * 16 + q];
            Pv = make_float2(ym.x + yn.x, ym.y + yn.y);
            Qv = make_float2(-(ym.y - yn.y), ym.x - yn.x);   // i*(Ym - Y-m)
        }
        ulonglong2 pq; pq.x = pack2(Pv.x, Pv.y); pq.y = pack2(Qv.x, Qv.y);
        PQ[mp * 16 + q] = pq;
    }
    if (tid < 16) {
        int q = tid;                         // mp = 16 (t = -16): Qv = -i*Y
        float2 y = Ys[16 * 16 + q];
        ulonglong2 pq; pq.x = pack2(y.x, y.y); pq.y = pack2(y.y, -y.x);
        PQ[16 * 16 + q] = pq;
    }
    __syncthreads();

    // Part 1: rows h0 and h0+128 share twiddles via parity of mp
    const u64 NEG1 = pack2(-1.0f, -1.0f);
    #pragma unroll 2
    for (int it = 0; it < 8; it++) {
        int task = tid + it * 256;           // 2048 = 128 h0 x 16 q
        int q = task & 15, h0 = task >> 4;
        u64 Se = 0ull, So = 0ull;
        #pragma unroll
        for (int mp = 0; mp <= 16; mp++) {
            ulonglong2 t  = tw2[(mp * h0) & 255];
            ulonglong2 pq = PQ[mp * 16 + q];
            if (mp & 1) { So = fma2(pq.x, t.x, So); So = fma2(pq.y, t.y, So); }
            else        { Se = fma2(pq.x, t.x, Se); Se = fma2(pq.y, t.y, Se); }
        }
        float a = (q == 0) ? (1.0f / 256.0f) : (2.0f / 256.0f);
        float2 v0 = unpack2(add2(Se, So));
        float2 v1 = unpack2(fma2(So, NEG1, Se));
        Gp[q * 258 + h0]       = make_float2(a * v0.x, -a * v0.y);
        Gp[q * 258 + h0 + 128] = make_float2(a * v1.x, -a * v1.y);
    }
    __syncthreads();

    // Part 2: 2 w' columns per thread, 4 h-groups
    const int wa = tid & 63;
    const int wb = wa + 64;
    const int hg = tid >> 6;
    u64 twa[16], twb[16];
    #pragma unroll
    for (int q = 0; q < 16; q++) {
        twa[q] = twcs[(q * wa) & 255];
        twb[q] = twcs[(q * wb) & 255];
    }

    float* ob = out + bd * 65536;
    const int hbase = hg * 64;
    #pragma unroll 2
    for (int hh = hbase; hh < hbase + 64; hh += 2) {
        u64 ca0 = 0ull, ca1 = 0ull, cb0 = 0ull, cb1 = 0ull;
        #pragma unroll
        for (int q = 0; q < 16; q++) {
            ulonglong2 g = *(const ulonglong2*)&Gp[q * 258 + hh];  // broadcast
            ca0 = fma2(g.x, twa[q], ca0);
            ca1 = fma2(g.y, twa[q], ca1);
            cb0 = fma2(g.x, twb[q], cb0);
            cb1 = fma2(g.y, twb[q], cb1);
        }
        float2 ra0 = unpack2(ca0), ra1 = unpack2(ca1);
        float2 rb0 = unpack2(cb0), rb1 = unpack2(cb1);
        ob[hh * 256 + wa]             = ra0.x + ra0.y;
        ob[(hh + 1) * 256 + wa]       = ra1.x + ra1.y;
        ob[hh * 256 + wb]             = rb0.x + rb0.y;
        ob[(hh + 1) * 256 + wb]       = rb1.x + rb1.y;
        ob[hh * 256 + 256 - wb]       = rb0.x - rb0.y;
        ob[(hh + 1) * 256 + 256 - wb] = rb1.x - rb1.y;
        if (wa) {
            ob[hh * 256 + 256 - wa]       = ra0.x - ra0.y;
            ob[(hh + 1) * 256 + 256 - wa] = ra1.x - ra1.y;
        }
    }
    // w = 128 column: cos(pi q) = (-1)^q, sin = 0
    {
        int h = tid;
        float acc = 0.0f;
        #pragma unroll
        for (int q = 0; q < 16; q++) {
            float v = Gp[q * 258 + h].x;
            acc += (q & 1) ? -v : v;
        }
        ob[h * 256 + 128] = acc;
    }
}

extern "C" void kernel_launch(void* const* d_in, const int* in_sizes, int n_in,
                              void* d_out, int out_size) {
    const float* x  = (const float*)d_in[0];
    const float* w1 = (const float*)d_in[1];
    const float* w2 = (const float*)d_in[2];
    float* out = (float*)d_out;

    const int SMEM_AB = 67984;
    const int SMEM_M  = 1024 * 8 + 4096 * 16;          // 73728
    cudaFuncSetAttribute(kAB, cudaFuncAttributeMaxDynamicSharedMemorySize, SMEM_AB);
    cudaFuncSetAttribute(kM,  cudaFuncAttributeMaxDynamicSharedMemorySize, SMEM_M);

    kAB<<<NBC, 256, SMEM_AB>>>(x);
    kM<<<512, 256, SMEM_M>>>(w1, w2);
    kCD<<<NBC, 256>>>(out);
}